// round 8
// baseline (speedup 1.0000x reference)
#include <cuda_runtime.h>
#include <math.h>

using ull = unsigned long long;

constexpr int T_STEPS = 28;
constexpr int B_TOT   = 16384;
constexpr int X_DIM   = 28;
constexpr int H_DIM   = 100;
constexpr int Z_DIM   = 16;
constexpr int TB      = 64;              // batch rows per block (2 per lane)
constexpr int NBLK    = B_TOT / TB;      // 256 blocks, 2 per SM -> one wave
constexpr int NTHR    = 256;             // 8 warps

// Transposed weights (654,400 B) + reduction state
__device__ float        g_WT[163600];
__device__ float        g_part[NBLK * 2];
__device__ unsigned int g_done;

// WT segment offsets (floats): WT[off + k*N + o] = W[o*K + k]
constexpr int O_Wpx  = 0;       // N=100 K=28
constexpr int O_Wpz  = 2800;    // N=100 K=16
constexpr int O_Wp1  = 4400;    // N=100 K=100
constexpr int O_Wpmu = 14400;   // N=16  K=100
constexpr int O_Wpsg = 16000;
constexpr int O_Wemu = 17600;
constexpr int O_Wesg = 19200;
constexpr int O_We1  = 20800;   // N=100 K=200
constexpr int O_Wd1  = 40800;   // N=100 K=200
constexpr int O_Wd2  = 60800;   // N=100 K=100
constexpr int O_Wd3  = 70800;   // N=28  K=100
constexpr int O_Wih  = 73600;   // N=300 K=200
constexpr int O_Whh  = 133600;  // N=300 K=100

enum { ACT_LIN = 0, ACT_RELU = 1, ACT_SIG = 2, ACT_SP = 3 };

__device__ __forceinline__ float act_apply(float v, int A) {
    if (A == ACT_RELU) return fmaxf(v, 0.f);
    if (A == ACT_SIG)  return 1.f / (1.f + expf(-v));
    if (A == ACT_SP)   return fmaxf(v, 0.f) + log1pf(expf(-fabsf(v)));
    return v;
}
__device__ __forceinline__ float sigf(float v) { return 1.f / (1.f + expf(-v)); }

__device__ __forceinline__ ull b2(float v) {
    ull r; asm("mov.b64 %0,{%1,%1};" : "=l"(r) : "f"(v)); return r;
}
__device__ __forceinline__ ull fma2(ull a, ull b, ull c) {
    ull d; asm("fma.rn.f32x2 %0,%1,%2,%3;" : "=l"(d) : "l"(a), "l"(b), "l"(c));
    return d;
}
__device__ __forceinline__ float2 unpk(ull v) {
    float2 f; asm("mov.b64 {%0,%1},%2;" : "=f"(f.x), "=f"(f.y) : "l"(v)); return f;
}
__device__ __forceinline__ ull pk(float x, float y) {
    ull r; asm("mov.b64 %0,{%1,%2};" : "=l"(r) : "f"(x), "f"(y)); return r;
}

// ---------------------------------------------------------------------------
// Prep: transpose all weight matrices into g_WT (cheap, graph-capturable).
__global__ void prep_transpose(
    const float* __restrict__ Wpx, const float* __restrict__ Wpz,
    const float* __restrict__ Wp1, const float* __restrict__ Wpmu,
    const float* __restrict__ Wpsg, const float* __restrict__ Wemu,
    const float* __restrict__ Wesg, const float* __restrict__ We1,
    const float* __restrict__ Wd1, const float* __restrict__ Wd2,
    const float* __restrict__ Wd3, const float* __restrict__ Wih,
    const float* __restrict__ Whh)
{
    for (int idx = blockIdx.x * blockDim.x + threadIdx.x; idx < 163600;
         idx += gridDim.x * blockDim.x) {
        const float* W; int N, K, off;
        if      (idx < O_Wpz ) { W = Wpx;  N = 100; K = 28;  off = O_Wpx;  }
        else if (idx < O_Wp1 ) { W = Wpz;  N = 100; K = 16;  off = O_Wpz;  }
        else if (idx < O_Wpmu) { W = Wp1;  N = 100; K = 100; off = O_Wp1;  }
        else if (idx < O_Wpsg) { W = Wpmu; N = 16;  K = 100; off = O_Wpmu; }
        else if (idx < O_Wemu) { W = Wpsg; N = 16;  K = 100; off = O_Wpsg; }
        else if (idx < O_Wesg) { W = Wemu; N = 16;  K = 100; off = O_Wemu; }
        else if (idx < O_We1 ) { W = Wesg; N = 16;  K = 100; off = O_Wesg; }
        else if (idx < O_Wd1 ) { W = We1;  N = 100; K = 200; off = O_We1;  }
        else if (idx < O_Wd2 ) { W = Wd1;  N = 100; K = 200; off = O_Wd1;  }
        else if (idx < O_Wd3 ) { W = Wd2;  N = 100; K = 100; off = O_Wd2;  }
        else if (idx < O_Wih ) { W = Wd3;  N = 28;  K = 100; off = O_Wd3;  }
        else if (idx < O_Whh ) { W = Wih;  N = 300; K = 200; off = O_Wih;  }
        else                   { W = Whh;  N = 300; K = 100; off = O_Whh;  }
        int l = idx - off;
        int k = l / N, o = l % N;
        g_WT[idx] = W[o * K + k];
    }
}

// ---------------------------------------------------------------------------
// gemmT: NQ quads (4 outputs each) with transposed weights.
// Activations feat-major packed: act_u64[k*32+lane] = rows (lane, lane+32).
// WTo pre-offset by o0 (column); o0 must be multiple of 4 (16B alignment).
template <int NQ, int KA, int KB, int ACT>
__device__ __forceinline__ void gemmT(
    const float* __restrict__ WTo, const float* __restrict__ bias, int o0,
    const float* __restrict__ actA, const float* __restrict__ actB,
    float* __restrict__ out, int lane)
{
    ull a0[2 * NQ], a1[2 * NQ];     // [pair]: rows lane / lane+32
#pragma unroll
    for (int i = 0; i < 2 * NQ; i++) { a0[i] = 0ull; a1[i] = 0ull; }

    {
        const ull* A = (const ull*)actA;
#pragma unroll 4
        for (int k = 0; k < KA; k++) {
            float2 f = unpk(A[k * 32 + lane]);
            ull r0 = b2(f.x), r1 = b2(f.y);
#pragma unroll
            for (int q = 0; q < NQ; q++) {
                ulonglong2 w = *(const ulonglong2*)(WTo + (size_t)k * 100 + 4 * q);
                a0[2*q]   = fma2(w.x, r0, a0[2*q]);
                a0[2*q+1] = fma2(w.y, r0, a0[2*q+1]);
                a1[2*q]   = fma2(w.x, r1, a1[2*q]);
                a1[2*q+1] = fma2(w.y, r1, a1[2*q+1]);
            }
        }
    }
    if constexpr (KB > 0) {
        const ull* A = (const ull*)actB;
#pragma unroll 4
        for (int k = 0; k < KB; k++) {
            float2 f = unpk(A[k * 32 + lane]);
            ull r0 = b2(f.x), r1 = b2(f.y);
#pragma unroll
            for (int q = 0; q < NQ; q++) {
                ulonglong2 w = *(const ulonglong2*)(WTo + (size_t)(KA + k) * 100 + 4 * q);
                a0[2*q]   = fma2(w.x, r0, a0[2*q]);
                a0[2*q+1] = fma2(w.y, r0, a0[2*q+1]);
                a1[2*q]   = fma2(w.x, r1, a1[2*q]);
                a1[2*q+1] = fma2(w.y, r1, a1[2*q+1]);
            }
        }
    }
    ull* o64 = (ull*)out;
#pragma unroll
    for (int p = 0; p < 2 * NQ; p++) {
        const int o = o0 + 2 * p;
        float2 v0 = unpk(a0[p]);     // outputs (o, o+1), row lane
        float2 v1 = unpk(a1[p]);     // row lane+32
        o64[o * 32 + lane]       = pk(act_apply(v0.x + bias[o], ACT),
                                      act_apply(v1.x + bias[o], ACT));
        o64[(o + 1) * 32 + lane] = pk(act_apply(v0.y + bias[o + 1], ACT),
                                      act_apply(v1.y + bias[o + 1], ACT));
    }
}

// 100 outputs = 25 quads over 8 warps: warps 0-6 -> 3 quads, warp 7 -> 4.
template <int KA, int KB, int ACT>
__device__ __forceinline__ void gemm100T(
    const float* __restrict__ WT, const float* __restrict__ bias,
    const float* aA, const float* aB, float* out, int warp, int lane)
{
    if (warp < 7)
        gemmT<3, KA, KB, ACT>(WT + 12 * warp, bias, 12 * warp, aA, aB, out, lane);
    else
        gemmT<4, KA, KB, ACT>(WT + 84, bias, 84, aA, aB, out, lane);
}

// ---------------------------------------------------------------------------
// Heads fused: all four K=100->16 heads + softplus + KL + z, registers only.
// Warp w handles output pair o0 = 2w (8 warps cover Z=16).
__device__ __forceinline__ void heads_fused(
    const float* __restrict__ he, const float* __restrict__ hp,
    const float* __restrict__ bem, const float* __restrict__ bes,
    const float* __restrict__ bpm, const float* __restrict__ bps,
    const float* __restrict__ eps_t, int b0, float* __restrict__ zb,
    int warp, int lane, float& kl_acc)
{
    const int o0 = 2 * warp;
    const float* WemT = g_WT + O_Wemu + o0;
    const float* WesT = g_WT + O_Wesg + o0;
    const float* WpmT = g_WT + O_Wpmu + o0;
    const float* WpsT = g_WT + O_Wpsg + o0;
    ull EM[2] = {0, 0}, ES[2] = {0, 0}, PM[2] = {0, 0}, PS[2] = {0, 0};
    const ull* He = (const ull*)he;
    const ull* Hp = (const ull*)hp;
#pragma unroll 4
    for (int k = 0; k < 100; k++) {
        float2 e = unpk(He[k * 32 + lane]);
        float2 q = unpk(Hp[k * 32 + lane]);
        ull e0 = b2(e.x), e1 = b2(e.y), q0 = b2(q.x), q1 = b2(q.y);
        ull wem = *(const ull*)(WemT + k * 16);
        ull wes = *(const ull*)(WesT + k * 16);
        ull wpm = *(const ull*)(WpmT + k * 16);
        ull wps = *(const ull*)(WpsT + k * 16);
        EM[0] = fma2(wem, e0, EM[0]); EM[1] = fma2(wem, e1, EM[1]);
        ES[0] = fma2(wes, e0, ES[0]); ES[1] = fma2(wes, e1, ES[1]);
        PM[0] = fma2(wpm, q0, PM[0]); PM[1] = fma2(wpm, q1, PM[1]);
        PS[0] = fma2(wps, q0, PS[0]); PS[1] = fma2(wps, q1, PS[1]);
    }
    ull* z64 = (ull*)zb;
#pragma unroll
    for (int e = 0; e < 2; e++) {
        const int o = o0 + e;
        float zv[2];
#pragma unroll
        for (int r = 0; r < 2; r++) {
            float2 em = unpk(EM[r]), es = unpk(ES[r]);
            float2 pm = unpk(PM[r]), ps = unpk(PS[r]);
            float emu = (e ? em.y : em.x) + bem[o];
            float esg = act_apply((e ? es.y : es.x) + bes[o], ACT_SP);
            float pmu = (e ? pm.y : pm.x) + bpm[o];
            float psg = act_apply((e ? ps.y : ps.x) + bps[o], ACT_SP);
            float psx = psg + 1e-10f;
            float d   = emu - pmu;
            kl_acc += 0.5f * (2.f * logf(psx) - 2.f * logf(esg)
                              + (esg * esg + d * d) / (psx * psx) - 1.f);
            const int row = lane + 32 * r;
            float ev = eps_t[(size_t)row * Z_DIM + o];
            zv[r] = emu + sqrtf(esg) * ev;
        }
        z64[o * 32 + lane] = pk(zv[0], zv[1]);
    }
    (void)b0;
}

// ---------------------------------------------------------------------------
// GRU: task = 4 adjacent j's. Transposed Wih[200][300]/Whh[100][300];
// gate columns r at +0, u at +100, n at +200.
__device__ __forceinline__ void gru_segT(
    ull (&R)[2][2], ull (&U)[2][2], ull (&NX)[2][2],
    const float* __restrict__ Wk, const float* __restrict__ act, int lane)
{
    const ull* A = (const ull*)act;
#pragma unroll 4
    for (int k = 0; k < 100; k++) {
        float2 f = unpk(A[k * 32 + lane]);
        ull r0 = b2(f.x), r1 = b2(f.y);
        const float* w = Wk + (size_t)k * 300;
        ulonglong2 wr = *(const ulonglong2*)(w);
        ulonglong2 wu = *(const ulonglong2*)(w + 100);
        ulonglong2 wn = *(const ulonglong2*)(w + 200);
        R[0][0]  = fma2(wr.x, r0, R[0][0]);  R[0][1]  = fma2(wr.x, r1, R[0][1]);
        R[1][0]  = fma2(wr.y, r0, R[1][0]);  R[1][1]  = fma2(wr.y, r1, R[1][1]);
        U[0][0]  = fma2(wu.x, r0, U[0][0]);  U[0][1]  = fma2(wu.x, r1, U[0][1]);
        U[1][0]  = fma2(wu.y, r0, U[1][0]);  U[1][1]  = fma2(wu.y, r1, U[1][1]);
        NX[0][0] = fma2(wn.x, r0, NX[0][0]); NX[0][1] = fma2(wn.x, r1, NX[0][1]);
        NX[1][0] = fma2(wn.y, r0, NX[1][0]); NX[1][1] = fma2(wn.y, r1, NX[1][1]);
    }
}

__device__ __forceinline__ void gru_task(
    int j0, const float* __restrict__ bih, const float* __restrict__ bhh,
    const float* __restrict__ pz, const float* __restrict__ px,
    const float* __restrict__ hc, float* __restrict__ hn, int lane)
{
    ull R[2][2], U[2][2], NI[2][2], NH[2][2];
#pragma unroll
    for (int p = 0; p < 2; p++)
#pragma unroll
        for (int r = 0; r < 2; r++) { R[p][r]=0; U[p][r]=0; NI[p][r]=0; NH[p][r]=0; }

    gru_segT(R, U, NI, g_WT + O_Wih + j0,             pz, lane);
    gru_segT(R, U, NI, g_WT + O_Wih + 100 * 300 + j0, px, lane);
    gru_segT(R, U, NH, g_WT + O_Whh + j0,             hc, lane);

    const ull* h64 = (const ull*)hc;
    ull* n64 = (ull*)hn;
#pragma unroll
    for (int jj = 0; jj < 4; jj++) {
        const int p = jj >> 1, e = jj & 1, j = j0 + jj;
        const float br = bih[j] + bhh[j];
        const float bu = bih[100 + j] + bhh[100 + j];
        const float bn = bih[200 + j];
        const float bm = bhh[200 + j];
        float2 H = unpk(h64[j * 32 + lane]);
        float ov[2];
#pragma unroll
        for (int r = 0; r < 2; r++) {
            float2 Rv = unpk(R[p][r]), Uv = unpk(U[p][r]);
            float2 Nv = unpk(NI[p][r]), Mv = unpk(NH[p][r]);
            float rv = e ? Rv.y : Rv.x;
            float uv = e ? Uv.y : Uv.x;
            float nv = e ? Nv.y : Nv.x;
            float mv = e ? Mv.y : Mv.x;
            float rr = sigf(rv + br);
            float uu = sigf(uv + bu);
            float nn = tanhf(nv + bn + rr * (mv + bm));
            float hv = r ? H.y : H.x;
            ov[r] = (1.f - uu) * nn + uu * hv;
        }
        n64[j * 32 + lane] = pk(ov[0], ov[1]);
    }
}

// ---------------------------------------------------------------------------
// Wd3 (28 outputs) + fused Bernoulli NLL; warps 0-6, one quad each.
__device__ __forceinline__ void wd3_nll(
    const float* __restrict__ bd3, const float* __restrict__ hd2,
    const float* __restrict__ xs, int o0, int lane, float& nll)
{
    ull a0[2] = {0, 0}, a1[2] = {0, 0};
    const ull* A = (const ull*)hd2;
    const float* WT3 = g_WT + O_Wd3 + o0;
#pragma unroll 4
    for (int k = 0; k < 100; k++) {
        float2 f = unpk(A[k * 32 + lane]);
        ull r0 = b2(f.x), r1 = b2(f.y);
        ulonglong2 w = *(const ulonglong2*)(WT3 + k * 28);
        a0[0] = fma2(w.x, r0, a0[0]); a0[1] = fma2(w.y, r0, a0[1]);
        a1[0] = fma2(w.x, r1, a1[0]); a1[1] = fma2(w.y, r1, a1[1]);
    }
    const ull* X = (const ull*)xs;
#pragma unroll
    for (int p = 0; p < 2; p++) {
        float2 v0 = unpk(a0[p]);
        float2 v1 = unpk(a1[p]);
#pragma unroll
        for (int e = 0; e < 2; e++) {
            const int o = o0 + 2 * p + e;
            float p0 = sigf((e ? v0.y : v0.x) + bd3[o]);
            float p1 = sigf((e ? v1.y : v1.x) + bd3[o]);
            float2 xv = unpk(X[o * 32 + lane]);
            nll -= xv.x * logf(p0 + 1e-10f) + (1.f - xv.x) * logf(1.f - p0 + 1e-10f);
            nll -= xv.y * logf(p1 + 1e-10f) + (1.f - xv.y) * logf(1.f - p1 + 1e-10f);
        }
    }
}

// ---------------------------------------------------------------------------
__global__ void __launch_bounds__(NTHR, 2) vrnn_main(
    const float* __restrict__ x,      const float* __restrict__ eps,
    const float* __restrict__ bpx,    const float* __restrict__ bpz,
    const float* __restrict__ bp1,    const float* __restrict__ bp_mu,
    const float* __restrict__ bp_sig, const float* __restrict__ be1,
    const float* __restrict__ be_mu,  const float* __restrict__ be_sig,
    const float* __restrict__ bd1,    const float* __restrict__ bd2,
    const float* __restrict__ bd3,    const float* __restrict__ bih,
    const float* __restrict__ bhh,    float* __restrict__ out)
{
    extern __shared__ float s[];
    float* xs = s;                        // 28*64
    float* zb = xs + X_DIM * TB;          // 16*64
    float* H0 = zb + Z_DIM * TB;          // 4 x 100*64
    float* H1 = H0 + H_DIM * TB;
    float* H2 = H1 + H_DIM * TB;
    float* H3 = H2 + H_DIM * TB;

    __shared__ int s_last;

    const int tid  = threadIdx.x;
    const int lane = tid & 31;
    const int warp = tid >> 5;
    const int b0   = blockIdx.x * TB;

    float* hc  = H0;   // current h
    float* pxb = H1;   // px / hd1
    float* s1  = H2;   // he / pz
    float* s2  = H3;   // hp / hn

    for (int i = tid; i < H_DIM * TB; i += NTHR) hc[i] = 0.f;

    float kl_acc = 0.f, nll_acc = 0.f;

    for (int t = 0; t < T_STEPS; t++) {
        const float* xg  = x   + ((size_t)t * B_TOT + b0) * X_DIM;
        const float* ept = eps + ((size_t)t * B_TOT + b0) * Z_DIM;
        for (int i = tid; i < X_DIM * TB; i += NTHR) {
            int r = i / X_DIM, k = i % X_DIM;
            xs[(k * 32 + (r & 31)) * 2 + (r >> 5)] = xg[i];
        }
        __syncthreads();

        // 1. px = relu(Wpx x + b)
        gemm100T<28, 0, ACT_RELU>(g_WT + O_Wpx, bpx, xs, nullptr, pxb, warp, lane);
        __syncthreads();

        // 2+3. he = relu(We1 [px;h]) -> s1 ; hp = relu(Wp1 h) -> s2
        gemm100T<100, 100, ACT_RELU>(g_WT + O_We1, be1, pxb, hc, s1, warp, lane);
        gemm100T<100, 0,   ACT_RELU>(g_WT + O_Wp1, bp1, hc, nullptr, s2, warp, lane);
        __syncthreads();

        // 4. heads + KL + z (registers only)
        heads_fused(s1, s2, be_mu, be_sig, bp_mu, bp_sig, ept, b0, zb,
                    warp, lane, kl_acc);
        __syncthreads();

        // 5. pz = relu(Wpz z + b) -> s1
        gemm100T<16, 0, ACT_RELU>(g_WT + O_Wpz, bpz, zb, nullptr, s1, warp, lane);
        __syncthreads();

        // 6. GRU(pz, px, h) -> hn into s2
        for (int t4 = warp; t4 < 25; t4 += 8)
            gru_task(4 * t4, bih, bhh, s1, pxb, hc, s2, lane);
        __syncthreads();

        // 7. hd1 = relu(Wd1 [pz;h]) -> pxb (px dead after GRU)
        gemm100T<100, 100, ACT_RELU>(g_WT + O_Wd1, bd1, s1, hc, pxb, warp, lane);
        __syncthreads();

        // 8. hd2 = relu(Wd2 hd1) -> hc buffer (h dead after stage 7)
        gemm100T<100, 0, ACT_RELU>(g_WT + O_Wd2, bd2, pxb, nullptr, hc, warp, lane);
        __syncthreads();

        // 9. Wd3 + fused NLL (warps 0-6)
        if (warp < 7)
            wd3_nll(bd3, hc, xs, 4 * warp, lane, nll_acc);

        // rotate: new h = hn (s2); old hc buffer becomes scratch
        { float* tmp = hc; hc = s2; s2 = tmp; }
        __syncthreads();
    }

    // ---- block partial reduction (8 warps)
#pragma unroll
    for (int off = 16; off > 0; off >>= 1) {
        kl_acc  += __shfl_down_sync(0xffffffffu, kl_acc,  off);
        nll_acc += __shfl_down_sync(0xffffffffu, nll_acc, off);
    }
    if (lane == 0) { s[warp] = kl_acc; s[8 + warp] = nll_acc; }
    __syncthreads();
    if (tid == 0) {
        float k = 0.f, n = 0.f;
        for (int w = 0; w < 8; w++) { k += s[w]; n += s[8 + w]; }
        g_part[2 * blockIdx.x + 0] = k;
        g_part[2 * blockIdx.x + 1] = n;
        __threadfence();
        unsigned v = atomicAdd(&g_done, 1u);
        s_last = (v == (unsigned)(gridDim.x - 1)) ? 1 : 0;
    }
    __syncthreads();

    // ---- deterministic final reduction in the last-arriving block
    if (s_last) {
        s[tid]       = g_part[2 * tid + 0];   // NBLK == NTHR == 256
        s[256 + tid] = g_part[2 * tid + 1];
        __syncthreads();
        for (int st = 128; st > 0; st >>= 1) {
            if (tid < st) { s[tid] += s[tid + st]; s[256 + tid] += s[256 + tid + st]; }
            __syncthreads();
        }
        if (tid == 0) {
            const float invB = 1.f / (float)B_TOT;
            out[0] = s[0] * invB;
            out[1] = s[256] * invB;
            g_done = 0;                  // reset for next graph replay
        }
    }
}

// ---------------------------------------------------------------------------
extern "C" void kernel_launch(void* const* d_in, const int* in_sizes, int n_in,
                              void* d_out, int out_size)
{
    (void)in_sizes; (void)n_in; (void)out_size;
    const float* x      = (const float*)d_in[0];
    const float* eps    = (const float*)d_in[1];
    const float* Wpx    = (const float*)d_in[2];
    const float* bpx    = (const float*)d_in[3];
    const float* Wpz    = (const float*)d_in[4];
    const float* bpz    = (const float*)d_in[5];
    const float* Wp1    = (const float*)d_in[6];
    const float* bp1    = (const float*)d_in[7];
    const float* Wp_mu  = (const float*)d_in[8];
    const float* bp_mu  = (const float*)d_in[9];
    const float* Wp_sig = (const float*)d_in[10];
    const float* bp_sig = (const float*)d_in[11];
    const float* We1    = (const float*)d_in[12];
    const float* be1    = (const float*)d_in[13];
    const float* We_mu  = (const float*)d_in[14];
    const float* be_mu  = (const float*)d_in[15];
    const float* We_sig = (const float*)d_in[16];
    const float* be_sig = (const float*)d_in[17];
    const float* Wd1    = (const float*)d_in[18];
    const float* bd1    = (const float*)d_in[19];
    const float* Wd2    = (const float*)d_in[20];
    const float* bd2    = (const float*)d_in[21];
    const float* Wd3    = (const float*)d_in[22];
    const float* bd3    = (const float*)d_in[23];
    const float* Wih    = (const float*)d_in[24];
    const float* Whh    = (const float*)d_in[25];
    const float* bih    = (const float*)d_in[26];
    const float* bhh    = (const float*)d_in[27];
    float* out = (float*)d_out;

    prep_transpose<<<160, 256>>>(Wpx, Wpz, Wp1, Wp_mu, Wp_sig, We_mu, We_sig,
                                 We1, Wd1, Wd2, Wd3, Wih, Whh);

    const int smem_floats = X_DIM * TB + Z_DIM * TB + 4 * H_DIM * TB;  // 28,416
    const int smem_bytes  = smem_floats * (int)sizeof(float);          // 113,664

    cudaFuncSetAttribute(vrnn_main,
                         cudaFuncAttributeMaxDynamicSharedMemorySize, smem_bytes);

    vrnn_main<<<NBLK, NTHR, smem_bytes>>>(
        x, eps, bpx, bpz, bp1, bp_mu, bp_sig, be1, be_mu, be_sig,
        bd1, bd2, bd3, bih, bhh, out);
}

// round 9
// speedup vs baseline: 1.0004x; 1.0004x over previous
#include <cuda_runtime.h>
#include <math.h>

using ull = unsigned long long;

constexpr int T_STEPS = 28;
constexpr int B_TOT   = 16384;
constexpr int X_DIM   = 28;
constexpr int H_DIM   = 100;
constexpr int Z_DIM   = 16;
constexpr int TB      = 64;              // batch rows per block (2 per lane)
constexpr int NBLK    = B_TOT / TB;      // 256 blocks, 2 per SM -> one wave
constexpr int NTHR    = 256;             // 8 warps

// Transposed weights (654,400 B) + reduction state
__device__ float        g_WT[163600];
__device__ float        g_part[NBLK * 2];
__device__ unsigned int g_done;

// WT segment offsets (floats): WT[off + k*N + o] = W[o*K + k]
constexpr int O_Wpx  = 0;       // N=100 K=28
constexpr int O_Wpz  = 2800;    // N=100 K=16
constexpr int O_Wp1  = 4400;    // N=100 K=100
constexpr int O_Wpmu = 14400;   // N=16  K=100
constexpr int O_Wpsg = 16000;
constexpr int O_Wemu = 17600;
constexpr int O_Wesg = 19200;
constexpr int O_We1  = 20800;   // N=100 K=200
constexpr int O_Wd1  = 40800;   // N=100 K=200
constexpr int O_Wd2  = 60800;   // N=100 K=100
constexpr int O_Wd3  = 70800;   // N=28  K=100
constexpr int O_Wih  = 73600;   // N=300 K=200
constexpr int O_Whh  = 133600;  // N=300 K=100

enum { ACT_LIN = 0, ACT_RELU = 1, ACT_SIG = 2, ACT_SP = 3 };

__device__ __forceinline__ float act_apply(float v, int A) {
    if (A == ACT_RELU) return fmaxf(v, 0.f);
    if (A == ACT_SIG)  return 1.f / (1.f + expf(-v));
    if (A == ACT_SP)   return fmaxf(v, 0.f) + log1pf(expf(-fabsf(v)));
    return v;
}
__device__ __forceinline__ float sigf(float v) { return 1.f / (1.f + expf(-v)); }

__device__ __forceinline__ ull b2(float v) {
    ull r; asm("mov.b64 %0,{%1,%1};" : "=l"(r) : "f"(v)); return r;
}
__device__ __forceinline__ ull fma2(ull a, ull b, ull c) {
    ull d; asm("fma.rn.f32x2 %0,%1,%2,%3;" : "=l"(d) : "l"(a), "l"(b), "l"(c));
    return d;
}
__device__ __forceinline__ float2 unpk(ull v) {
    float2 f; asm("mov.b64 {%0,%1},%2;" : "=f"(f.x), "=f"(f.y) : "l"(v)); return f;
}
__device__ __forceinline__ ull pk(float x, float y) {
    ull r; asm("mov.b64 %0,{%1,%2};" : "=l"(r) : "f"(x), "f"(y)); return r;
}

// ---------------------------------------------------------------------------
// Prep: transpose all weight matrices into g_WT (cheap, graph-capturable).
__global__ void prep_transpose(
    const float* __restrict__ Wpx, const float* __restrict__ Wpz,
    const float* __restrict__ Wp1, const float* __restrict__ Wpmu,
    const float* __restrict__ Wpsg, const float* __restrict__ Wemu,
    const float* __restrict__ Wesg, const float* __restrict__ We1,
    const float* __restrict__ Wd1, const float* __restrict__ Wd2,
    const float* __restrict__ Wd3, const float* __restrict__ Wih,
    const float* __restrict__ Whh)
{
    for (int idx = blockIdx.x * blockDim.x + threadIdx.x; idx < 163600;
         idx += gridDim.x * blockDim.x) {
        const float* W; int N, K, off;
        if      (idx < O_Wpz ) { W = Wpx;  N = 100; K = 28;  off = O_Wpx;  }
        else if (idx < O_Wp1 ) { W = Wpz;  N = 100; K = 16;  off = O_Wpz;  }
        else if (idx < O_Wpmu) { W = Wp1;  N = 100; K = 100; off = O_Wp1;  }
        else if (idx < O_Wpsg) { W = Wpmu; N = 16;  K = 100; off = O_Wpmu; }
        else if (idx < O_Wemu) { W = Wpsg; N = 16;  K = 100; off = O_Wpsg; }
        else if (idx < O_Wesg) { W = Wemu; N = 16;  K = 100; off = O_Wemu; }
        else if (idx < O_We1 ) { W = Wesg; N = 16;  K = 100; off = O_Wesg; }
        else if (idx < O_Wd1 ) { W = We1;  N = 100; K = 200; off = O_We1;  }
        else if (idx < O_Wd2 ) { W = Wd1;  N = 100; K = 200; off = O_Wd1;  }
        else if (idx < O_Wd3 ) { W = Wd2;  N = 100; K = 100; off = O_Wd2;  }
        else if (idx < O_Wih ) { W = Wd3;  N = 28;  K = 100; off = O_Wd3;  }
        else if (idx < O_Whh ) { W = Wih;  N = 300; K = 200; off = O_Wih;  }
        else                   { W = Whh;  N = 300; K = 100; off = O_Whh;  }
        int l = idx - off;
        int k = l / N, o = l % N;
        g_WT[idx] = W[o * K + k];
    }
}

// ---------------------------------------------------------------------------
// gemmT: NQ quads (4 outputs each) with transposed weights.
// Activations feat-major packed: act_u64[k*32+lane] = rows (lane, lane+32).
// WTo pre-offset by o0 (column); o0 must be multiple of 4 (16B alignment).
template <int NQ, int KA, int KB, int ACT>
__device__ __forceinline__ void gemmT(
    const float* __restrict__ WTo, const float* __restrict__ bias, int o0,
    const float* __restrict__ actA, const float* __restrict__ actB,
    float* __restrict__ out, int lane)
{
    ull a0[2 * NQ], a1[2 * NQ];     // [pair]: rows lane / lane+32
#pragma unroll
    for (int i = 0; i < 2 * NQ; i++) { a0[i] = 0ull; a1[i] = 0ull; }

    {
        const ull* A = (const ull*)actA;
#pragma unroll 4
        for (int k = 0; k < KA; k++) {
            float2 f = unpk(A[k * 32 + lane]);
            ull r0 = b2(f.x), r1 = b2(f.y);
#pragma unroll
            for (int q = 0; q < NQ; q++) {
                ulonglong2 w = *(const ulonglong2*)(WTo + (size_t)k * 100 + 4 * q);
                a0[2*q]   = fma2(w.x, r0, a0[2*q]);
                a0[2*q+1] = fma2(w.y, r0, a0[2*q+1]);
                a1[2*q]   = fma2(w.x, r1, a1[2*q]);
                a1[2*q+1] = fma2(w.y, r1, a1[2*q+1]);
            }
        }
    }
    if constexpr (KB > 0) {
        const ull* A = (const ull*)actB;
#pragma unroll 4
        for (int k = 0; k < KB; k++) {
            float2 f = unpk(A[k * 32 + lane]);
            ull r0 = b2(f.x), r1 = b2(f.y);
#pragma unroll
            for (int q = 0; q < NQ; q++) {
                ulonglong2 w = *(const ulonglong2*)(WTo + (size_t)(KA + k) * 100 + 4 * q);
                a0[2*q]   = fma2(w.x, r0, a0[2*q]);
                a0[2*q+1] = fma2(w.y, r0, a0[2*q+1]);
                a1[2*q]   = fma2(w.x, r1, a1[2*q]);
                a1[2*q+1] = fma2(w.y, r1, a1[2*q+1]);
            }
        }
    }
    ull* o64 = (ull*)out;
#pragma unroll
    for (int p = 0; p < 2 * NQ; p++) {
        const int o = o0 + 2 * p;
        float2 v0 = unpk(a0[p]);     // outputs (o, o+1), row lane
        float2 v1 = unpk(a1[p]);     // row lane+32
        o64[o * 32 + lane]       = pk(act_apply(v0.x + bias[o], ACT),
                                      act_apply(v1.x + bias[o], ACT));
        o64[(o + 1) * 32 + lane] = pk(act_apply(v0.y + bias[o + 1], ACT),
                                      act_apply(v1.y + bias[o + 1], ACT));
    }
}

// 100 outputs = 25 quads over 8 warps: warps 0-6 -> 3 quads, warp 7 -> 4.
template <int KA, int KB, int ACT>
__device__ __forceinline__ void gemm100T(
    const float* __restrict__ WT, const float* __restrict__ bias,
    const float* aA, const float* aB, float* out, int warp, int lane)
{
    if (warp < 7)
        gemmT<3, KA, KB, ACT>(WT + 12 * warp, bias, 12 * warp, aA, aB, out, lane);
    else
        gemmT<4, KA, KB, ACT>(WT + 84, bias, 84, aA, aB, out, lane);
}

// ---------------------------------------------------------------------------
// Heads fused: all four K=100->16 heads + softplus + KL + z, registers only.
// Warp w handles output pair o0 = 2w (8 warps cover Z=16).
__device__ __forceinline__ void heads_fused(
    const float* __restrict__ he, const float* __restrict__ hp,
    const float* __restrict__ bem, const float* __restrict__ bes,
    const float* __restrict__ bpm, const float* __restrict__ bps,
    const float* __restrict__ eps_t, int b0, float* __restrict__ zb,
    int warp, int lane, float& kl_acc)
{
    const int o0 = 2 * warp;
    const float* WemT = g_WT + O_Wemu + o0;
    const float* WesT = g_WT + O_Wesg + o0;
    const float* WpmT = g_WT + O_Wpmu + o0;
    const float* WpsT = g_WT + O_Wpsg + o0;
    ull EM[2] = {0, 0}, ES[2] = {0, 0}, PM[2] = {0, 0}, PS[2] = {0, 0};
    const ull* He = (const ull*)he;
    const ull* Hp = (const ull*)hp;
#pragma unroll 4
    for (int k = 0; k < 100; k++) {
        float2 e = unpk(He[k * 32 + lane]);
        float2 q = unpk(Hp[k * 32 + lane]);
        ull e0 = b2(e.x), e1 = b2(e.y), q0 = b2(q.x), q1 = b2(q.y);
        ull wem = *(const ull*)(WemT + k * 16);
        ull wes = *(const ull*)(WesT + k * 16);
        ull wpm = *(const ull*)(WpmT + k * 16);
        ull wps = *(const ull*)(WpsT + k * 16);
        EM[0] = fma2(wem, e0, EM[0]); EM[1] = fma2(wem, e1, EM[1]);
        ES[0] = fma2(wes, e0, ES[0]); ES[1] = fma2(wes, e1, ES[1]);
        PM[0] = fma2(wpm, q0, PM[0]); PM[1] = fma2(wpm, q1, PM[1]);
        PS[0] = fma2(wps, q0, PS[0]); PS[1] = fma2(wps, q1, PS[1]);
    }
    ull* z64 = (ull*)zb;
#pragma unroll
    for (int e = 0; e < 2; e++) {
        const int o = o0 + e;
        float zv[2];
#pragma unroll
        for (int r = 0; r < 2; r++) {
            float2 em = unpk(EM[r]), es = unpk(ES[r]);
            float2 pm = unpk(PM[r]), ps = unpk(PS[r]);
            float emu = (e ? em.y : em.x) + bem[o];
            float esg = act_apply((e ? es.y : es.x) + bes[o], ACT_SP);
            float pmu = (e ? pm.y : pm.x) + bpm[o];
            float psg = act_apply((e ? ps.y : ps.x) + bps[o], ACT_SP);
            float psx = psg + 1e-10f;
            float d   = emu - pmu;
            kl_acc += 0.5f * (2.f * logf(psx) - 2.f * logf(esg)
                              + (esg * esg + d * d) / (psx * psx) - 1.f);
            const int row = lane + 32 * r;
            float ev = eps_t[(size_t)row * Z_DIM + o];
            zv[r] = emu + sqrtf(esg) * ev;
        }
        z64[o * 32 + lane] = pk(zv[0], zv[1]);
    }
    (void)b0;
}

// ---------------------------------------------------------------------------
// GRU: task = 4 adjacent j's. Transposed Wih[200][300]/Whh[100][300];
// gate columns r at +0, u at +100, n at +200.
__device__ __forceinline__ void gru_segT(
    ull (&R)[2][2], ull (&U)[2][2], ull (&NX)[2][2],
    const float* __restrict__ Wk, const float* __restrict__ act, int lane)
{
    const ull* A = (const ull*)act;
#pragma unroll 4
    for (int k = 0; k < 100; k++) {
        float2 f = unpk(A[k * 32 + lane]);
        ull r0 = b2(f.x), r1 = b2(f.y);
        const float* w = Wk + (size_t)k * 300;
        ulonglong2 wr = *(const ulonglong2*)(w);
        ulonglong2 wu = *(const ulonglong2*)(w + 100);
        ulonglong2 wn = *(const ulonglong2*)(w + 200);
        R[0][0]  = fma2(wr.x, r0, R[0][0]);  R[0][1]  = fma2(wr.x, r1, R[0][1]);
        R[1][0]  = fma2(wr.y, r0, R[1][0]);  R[1][1]  = fma2(wr.y, r1, R[1][1]);
        U[0][0]  = fma2(wu.x, r0, U[0][0]);  U[0][1]  = fma2(wu.x, r1, U[0][1]);
        U[1][0]  = fma2(wu.y, r0, U[1][0]);  U[1][1]  = fma2(wu.y, r1, U[1][1]);
        NX[0][0] = fma2(wn.x, r0, NX[0][0]); NX[0][1] = fma2(wn.x, r1, NX[0][1]);
        NX[1][0] = fma2(wn.y, r0, NX[1][0]); NX[1][1] = fma2(wn.y, r1, NX[1][1]);
    }
}

__device__ __forceinline__ void gru_task(
    int j0, const float* __restrict__ bih, const float* __restrict__ bhh,
    const float* __restrict__ pz, const float* __restrict__ px,
    const float* __restrict__ hc, float* __restrict__ hn, int lane)
{
    ull R[2][2], U[2][2], NI[2][2], NH[2][2];
#pragma unroll
    for (int p = 0; p < 2; p++)
#pragma unroll
        for (int r = 0; r < 2; r++) { R[p][r]=0; U[p][r]=0; NI[p][r]=0; NH[p][r]=0; }

    gru_segT(R, U, NI, g_WT + O_Wih + j0,             pz, lane);
    gru_segT(R, U, NI, g_WT + O_Wih + 100 * 300 + j0, px, lane);
    gru_segT(R, U, NH, g_WT + O_Whh + j0,             hc, lane);

    const ull* h64 = (const ull*)hc;
    ull* n64 = (ull*)hn;
#pragma unroll
    for (int jj = 0; jj < 4; jj++) {
        const int p = jj >> 1, e = jj & 1, j = j0 + jj;
        const float br = bih[j] + bhh[j];
        const float bu = bih[100 + j] + bhh[100 + j];
        const float bn = bih[200 + j];
        const float bm = bhh[200 + j];
        float2 H = unpk(h64[j * 32 + lane]);
        float ov[2];
#pragma unroll
        for (int r = 0; r < 2; r++) {
            float2 Rv = unpk(R[p][r]), Uv = unpk(U[p][r]);
            float2 Nv = unpk(NI[p][r]), Mv = unpk(NH[p][r]);
            float rv = e ? Rv.y : Rv.x;
            float uv = e ? Uv.y : Uv.x;
            float nv = e ? Nv.y : Nv.x;
            float mv = e ? Mv.y : Mv.x;
            float rr = sigf(rv + br);
            float uu = sigf(uv + bu);
            float nn = tanhf(nv + bn + rr * (mv + bm));
            float hv = r ? H.y : H.x;
            ov[r] = (1.f - uu) * nn + uu * hv;
        }
        n64[j * 32 + lane] = pk(ov[0], ov[1]);
    }
}

// ---------------------------------------------------------------------------
// Wd3 (28 outputs) + fused Bernoulli NLL; warps 0-6, one quad each.
__device__ __forceinline__ void wd3_nll(
    const float* __restrict__ bd3, const float* __restrict__ hd2,
    const float* __restrict__ xs, int o0, int lane, float& nll)
{
    ull a0[2] = {0, 0}, a1[2] = {0, 0};
    const ull* A = (const ull*)hd2;
    const float* WT3 = g_WT + O_Wd3 + o0;
#pragma unroll 4
    for (int k = 0; k < 100; k++) {
        float2 f = unpk(A[k * 32 + lane]);
        ull r0 = b2(f.x), r1 = b2(f.y);
        ulonglong2 w = *(const ulonglong2*)(WT3 + k * 28);
        a0[0] = fma2(w.x, r0, a0[0]); a0[1] = fma2(w.y, r0, a0[1]);
        a1[0] = fma2(w.x, r1, a1[0]); a1[1] = fma2(w.y, r1, a1[1]);
    }
    const ull* X = (const ull*)xs;
#pragma unroll
    for (int p = 0; p < 2; p++) {
        float2 v0 = unpk(a0[p]);
        float2 v1 = unpk(a1[p]);
#pragma unroll
        for (int e = 0; e < 2; e++) {
            const int o = o0 + 2 * p + e;
            float p0 = sigf((e ? v0.y : v0.x) + bd3[o]);
            float p1 = sigf((e ? v1.y : v1.x) + bd3[o]);
            float2 xv = unpk(X[o * 32 + lane]);
            nll -= xv.x * logf(p0 + 1e-10f) + (1.f - xv.x) * logf(1.f - p0 + 1e-10f);
            nll -= xv.y * logf(p1 + 1e-10f) + (1.f - xv.y) * logf(1.f - p1 + 1e-10f);
        }
    }
}

// ---------------------------------------------------------------------------
__global__ void __launch_bounds__(NTHR, 2) vrnn_main(
    const float* __restrict__ x,      const float* __restrict__ eps,
    const float* __restrict__ bpx,    const float* __restrict__ bpz,
    const float* __restrict__ bp1,    const float* __restrict__ bp_mu,
    const float* __restrict__ bp_sig, const float* __restrict__ be1,
    const float* __restrict__ be_mu,  const float* __restrict__ be_sig,
    const float* __restrict__ bd1,    const float* __restrict__ bd2,
    const float* __restrict__ bd3,    const float* __restrict__ bih,
    const float* __restrict__ bhh,    float* __restrict__ out)
{
    extern __shared__ float s[];
    float* xs = s;                        // 28*64
    float* zb = xs + X_DIM * TB;          // 16*64
    float* H0 = zb + Z_DIM * TB;          // 4 x 100*64
    float* H1 = H0 + H_DIM * TB;
    float* H2 = H1 + H_DIM * TB;
    float* H3 = H2 + H_DIM * TB;

    __shared__ int s_last;

    const int tid  = threadIdx.x;
    const int lane = tid & 31;
    const int warp = tid >> 5;
    const int b0   = blockIdx.x * TB;

    float* hc  = H0;   // current h
    float* pxb = H1;   // px / hd1
    float* s1  = H2;   // he / pz
    float* s2  = H3;   // hp / hn

    for (int i = tid; i < H_DIM * TB; i += NTHR) hc[i] = 0.f;

    float kl_acc = 0.f, nll_acc = 0.f;

    for (int t = 0; t < T_STEPS; t++) {
        const float* xg  = x   + ((size_t)t * B_TOT + b0) * X_DIM;
        const float* ept = eps + ((size_t)t * B_TOT + b0) * Z_DIM;
        for (int i = tid; i < X_DIM * TB; i += NTHR) {
            int r = i / X_DIM, k = i % X_DIM;
            xs[(k * 32 + (r & 31)) * 2 + (r >> 5)] = xg[i];
        }
        __syncthreads();

        // 1. px = relu(Wpx x + b)
        gemm100T<28, 0, ACT_RELU>(g_WT + O_Wpx, bpx, xs, nullptr, pxb, warp, lane);
        __syncthreads();

        // 2+3. he = relu(We1 [px;h]) -> s1 ; hp = relu(Wp1 h) -> s2
        gemm100T<100, 100, ACT_RELU>(g_WT + O_We1, be1, pxb, hc, s1, warp, lane);
        gemm100T<100, 0,   ACT_RELU>(g_WT + O_Wp1, bp1, hc, nullptr, s2, warp, lane);
        __syncthreads();

        // 4. heads + KL + z (registers only)
        heads_fused(s1, s2, be_mu, be_sig, bp_mu, bp_sig, ept, b0, zb,
                    warp, lane, kl_acc);
        __syncthreads();

        // 5. pz = relu(Wpz z + b) -> s1
        gemm100T<16, 0, ACT_RELU>(g_WT + O_Wpz, bpz, zb, nullptr, s1, warp, lane);
        __syncthreads();

        // 6. GRU(pz, px, h) -> hn into s2
        for (int t4 = warp; t4 < 25; t4 += 8)
            gru_task(4 * t4, bih, bhh, s1, pxb, hc, s2, lane);
        __syncthreads();

        // 7. hd1 = relu(Wd1 [pz;h]) -> pxb (px dead after GRU)
        gemm100T<100, 100, ACT_RELU>(g_WT + O_Wd1, bd1, s1, hc, pxb, warp, lane);
        __syncthreads();

        // 8. hd2 = relu(Wd2 hd1) -> hc buffer (h dead after stage 7)
        gemm100T<100, 0, ACT_RELU>(g_WT + O_Wd2, bd2, pxb, nullptr, hc, warp, lane);
        __syncthreads();

        // 9. Wd3 + fused NLL (warps 0-6)
        if (warp < 7)
            wd3_nll(bd3, hc, xs, 4 * warp, lane, nll_acc);

        // rotate: new h = hn (s2); old hc buffer becomes scratch
        { float* tmp = hc; hc = s2; s2 = tmp; }
        __syncthreads();
    }

    // ---- block partial reduction (8 warps)
#pragma unroll
    for (int off = 16; off > 0; off >>= 1) {
        kl_acc  += __shfl_down_sync(0xffffffffu, kl_acc,  off);
        nll_acc += __shfl_down_sync(0xffffffffu, nll_acc, off);
    }
    if (lane == 0) { s[warp] = kl_acc; s[8 + warp] = nll_acc; }
    __syncthreads();
    if (tid == 0) {
        float k = 0.f, n = 0.f;
        for (int w = 0; w < 8; w++) { k += s[w]; n += s[8 + w]; }
        g_part[2 * blockIdx.x + 0] = k;
        g_part[2 * blockIdx.x + 1] = n;
        __threadfence();
        unsigned v = atomicAdd(&g_done, 1u);
        s_last = (v == (unsigned)(gridDim.x - 1)) ? 1 : 0;
    }
    __syncthreads();

    // ---- deterministic final reduction in the last-arriving block
    if (s_last) {
        s[tid]       = g_part[2 * tid + 0];   // NBLK == NTHR == 256
        s[256 + tid] = g_part[2 * tid + 1];
        __syncthreads();
        for (int st = 128; st > 0; st >>= 1) {
            if (tid < st) { s[tid] += s[tid + st]; s[256 + tid] += s[256 + tid + st]; }
            __syncthreads();
        }
        if (tid == 0) {
            const float invB = 1.f / (float)B_TOT;
            out[0] = s[0] * invB;
            out[1] = s[256] * invB;
            g_done = 0;                  // reset for next graph replay
        }
    }
}

// ---------------------------------------------------------------------------
extern "C" void kernel_launch(void* const* d_in, const int* in_sizes, int n_in,
                              void* d_out, int out_size)
{
    (void)in_sizes; (void)n_in; (void)out_size;
    const float* x      = (const float*)d_in[0];
    const float* eps    = (const float*)d_in[1];
    const float* Wpx    = (const float*)d_in[2];
    const float* bpx    = (const float*)d_in[3];
    const float* Wpz    = (const float*)d_in[4];
    const float* bpz    = (const float*)d_in[5];
    const float* Wp1    = (const float*)d_in[6];
    const float* bp1    = (const float*)d_in[7];
    const float* Wp_mu  = (const float*)d_in[8];
    const float* bp_mu  = (const float*)d_in[9];
    const float* Wp_sig = (const float*)d_in[10];
    const float* bp_sig = (const float*)d_in[11];
    const float* We1    = (const float*)d_in[12];
    const float* be1    = (const float*)d_in[13];
    const float* We_mu  = (const float*)d_in[14];
    const float* be_mu  = (const float*)d_in[15];
    const float* We_sig = (const float*)d_in[16];
    const float* be_sig = (const float*)d_in[17];
    const float* Wd1    = (const float*)d_in[18];
    const float* bd1    = (const float*)d_in[19];
    const float* Wd2    = (const float*)d_in[20];
    const float* bd2    = (const float*)d_in[21];
    const float* Wd3    = (const float*)d_in[22];
    const float* bd3    = (const float*)d_in[23];
    const float* Wih    = (const float*)d_in[24];
    const float* Whh    = (const float*)d_in[25];
    const float* bih    = (const float*)d_in[26];
    const float* bhh    = (const float*)d_in[27];
    float* out = (float*)d_out;

    prep_transpose<<<160, 256>>>(Wpx, Wpz, Wp1, Wp_mu, Wp_sig, We_mu, We_sig,
                                 We1, Wd1, Wd2, Wd3, Wih, Whh);

    const int smem_floats = X_DIM * TB + Z_DIM * TB + 4 * H_DIM * TB;  // 28,416
    const int smem_bytes  = smem_floats * (int)sizeof(float);          // 113,664

    cudaFuncSetAttribute(vrnn_main,
                         cudaFuncAttributeMaxDynamicSharedMemorySize, smem_bytes);

    vrnn_main<<<NBLK, NTHR, smem_bytes>>>(
        x, eps, bpx, bpz, bp1, bp_mu, bp_sig, be1, be_mu, be_sig,
        bd1, bd2, bd3, bih, bhh, out);
}

// round 10
// speedup vs baseline: 1.0026x; 1.0021x over previous
#include <cuda_runtime.h>
#include <math.h>

using ull = unsigned long long;

constexpr int T_STEPS = 28;
constexpr int B_TOT   = 16384;
constexpr int X_DIM   = 28;
constexpr int H_DIM   = 100;
constexpr int Z_DIM   = 16;
constexpr int TB      = 64;              // batch rows per block (2 per lane)
constexpr int NBLK    = B_TOT / TB;      // 256 blocks, 2 per SM -> one wave
constexpr int NTHR    = 256;             // 8 warps

// Transposed weights (654,400 B) + reduction state
__device__ float        g_WT[163600];
__device__ float        g_part[NBLK * 2];
__device__ unsigned int g_done;

// WT segment offsets (floats): WT[off + k*N + o] = W[o*K + k]
constexpr int O_Wpx  = 0;       // N=100 K=28
constexpr int O_Wpz  = 2800;    // N=100 K=16
constexpr int O_Wp1  = 4400;    // N=100 K=100
constexpr int O_Wpmu = 14400;   // N=16  K=100
constexpr int O_Wpsg = 16000;
constexpr int O_Wemu = 17600;
constexpr int O_Wesg = 19200;
constexpr int O_We1  = 20800;   // N=100 K=200
constexpr int O_Wd1  = 40800;   // N=100 K=200
constexpr int O_Wd2  = 60800;   // N=100 K=100
constexpr int O_Wd3  = 70800;   // N=28  K=100
constexpr int O_Wih  = 73600;   // N=300 K=200
constexpr int O_Whh  = 133600;  // N=300 K=100

enum { ACT_LIN = 0, ACT_RELU = 1, ACT_SIG = 2, ACT_SP = 3 };

__device__ __forceinline__ float act_apply(float v, int A) {
    if (A == ACT_RELU) return fmaxf(v, 0.f);
    if (A == ACT_SIG)  return 1.f / (1.f + expf(-v));
    if (A == ACT_SP)   return fmaxf(v, 0.f) + log1pf(expf(-fabsf(v)));
    return v;
}
__device__ __forceinline__ float sigf(float v) { return 1.f / (1.f + expf(-v)); }

__device__ __forceinline__ ull b2(float v) {
    ull r; asm("mov.b64 %0,{%1,%1};" : "=l"(r) : "f"(v)); return r;
}
__device__ __forceinline__ ull fma2(ull a, ull b, ull c) {
    ull d; asm("fma.rn.f32x2 %0,%1,%2,%3;" : "=l"(d) : "l"(a), "l"(b), "l"(c));
    return d;
}
__device__ __forceinline__ float2 unpk(ull v) {
    float2 f; asm("mov.b64 {%0,%1},%2;" : "=f"(f.x), "=f"(f.y) : "l"(v)); return f;
}
__device__ __forceinline__ ull pk(float x, float y) {
    ull r; asm("mov.b64 %0,{%1,%2};" : "=l"(r) : "f"(x), "f"(y)); return r;
}

// ---------------------------------------------------------------------------
// Prep: transpose all weight matrices into g_WT (cheap, graph-capturable).
__global__ void prep_transpose(
    const float* __restrict__ Wpx, const float* __restrict__ Wpz,
    const float* __restrict__ Wp1, const float* __restrict__ Wpmu,
    const float* __restrict__ Wpsg, const float* __restrict__ Wemu,
    const float* __restrict__ Wesg, const float* __restrict__ We1,
    const float* __restrict__ Wd1, const float* __restrict__ Wd2,
    const float* __restrict__ Wd3, const float* __restrict__ Wih,
    const float* __restrict__ Whh)
{
    for (int idx = blockIdx.x * blockDim.x + threadIdx.x; idx < 163600;
         idx += gridDim.x * blockDim.x) {
        const float* W; int N, K, off;
        if      (idx < O_Wpz ) { W = Wpx;  N = 100; K = 28;  off = O_Wpx;  }
        else if (idx < O_Wp1 ) { W = Wpz;  N = 100; K = 16;  off = O_Wpz;  }
        else if (idx < O_Wpmu) { W = Wp1;  N = 100; K = 100; off = O_Wp1;  }
        else if (idx < O_Wpsg) { W = Wpmu; N = 16;  K = 100; off = O_Wpmu; }
        else if (idx < O_Wemu) { W = Wpsg; N = 16;  K = 100; off = O_Wpsg; }
        else if (idx < O_Wesg) { W = Wemu; N = 16;  K = 100; off = O_Wemu; }
        else if (idx < O_We1 ) { W = Wesg; N = 16;  K = 100; off = O_Wesg; }
        else if (idx < O_Wd1 ) { W = We1;  N = 100; K = 200; off = O_We1;  }
        else if (idx < O_Wd2 ) { W = Wd1;  N = 100; K = 200; off = O_Wd1;  }
        else if (idx < O_Wd3 ) { W = Wd2;  N = 100; K = 100; off = O_Wd2;  }
        else if (idx < O_Wih ) { W = Wd3;  N = 28;  K = 100; off = O_Wd3;  }
        else if (idx < O_Whh ) { W = Wih;  N = 300; K = 200; off = O_Wih;  }
        else                   { W = Whh;  N = 300; K = 100; off = O_Whh;  }
        int l = idx - off;
        int k = l / N, o = l % N;
        g_WT[idx] = W[o * K + k];
    }
}

// ---------------------------------------------------------------------------
// gemmT: NQ quads (4 outputs each) with transposed weights.
// Activations feat-major packed: act_u64[k*32+lane] = rows (lane, lane+32).
// WTo pre-offset by o0 (column); o0 must be multiple of 4 (16B alignment).
template <int NQ, int KA, int KB, int ACT>
__device__ __forceinline__ void gemmT(
    const float* __restrict__ WTo, const float* __restrict__ bias, int o0,
    const float* __restrict__ actA, const float* __restrict__ actB,
    float* __restrict__ out, int lane)
{
    ull a0[2 * NQ], a1[2 * NQ];     // [pair]: rows lane / lane+32
#pragma unroll
    for (int i = 0; i < 2 * NQ; i++) { a0[i] = 0ull; a1[i] = 0ull; }

    {
        const ull* A = (const ull*)actA;
#pragma unroll 4
        for (int k = 0; k < KA; k++) {
            float2 f = unpk(A[k * 32 + lane]);
            ull r0 = b2(f.x), r1 = b2(f.y);
#pragma unroll
            for (int q = 0; q < NQ; q++) {
                ulonglong2 w = *(const ulonglong2*)(WTo + (size_t)k * 100 + 4 * q);
                a0[2*q]   = fma2(w.x, r0, a0[2*q]);
                a0[2*q+1] = fma2(w.y, r0, a0[2*q+1]);
                a1[2*q]   = fma2(w.x, r1, a1[2*q]);
                a1[2*q+1] = fma2(w.y, r1, a1[2*q+1]);
            }
        }
    }
    if constexpr (KB > 0) {
        const ull* A = (const ull*)actB;
#pragma unroll 4
        for (int k = 0; k < KB; k++) {
            float2 f = unpk(A[k * 32 + lane]);
            ull r0 = b2(f.x), r1 = b2(f.y);
#pragma unroll
            for (int q = 0; q < NQ; q++) {
                ulonglong2 w = *(const ulonglong2*)(WTo + (size_t)(KA + k) * 100 + 4 * q);
                a0[2*q]   = fma2(w.x, r0, a0[2*q]);
                a0[2*q+1] = fma2(w.y, r0, a0[2*q+1]);
                a1[2*q]   = fma2(w.x, r1, a1[2*q]);
                a1[2*q+1] = fma2(w.y, r1, a1[2*q+1]);
            }
        }
    }
    ull* o64 = (ull*)out;
#pragma unroll
    for (int p = 0; p < 2 * NQ; p++) {
        const int o = o0 + 2 * p;
        float2 v0 = unpk(a0[p]);     // outputs (o, o+1), row lane
        float2 v1 = unpk(a1[p]);     // row lane+32
        o64[o * 32 + lane]       = pk(act_apply(v0.x + bias[o], ACT),
                                      act_apply(v1.x + bias[o], ACT));
        o64[(o + 1) * 32 + lane] = pk(act_apply(v0.y + bias[o + 1], ACT),
                                      act_apply(v1.y + bias[o + 1], ACT));
    }
}

// 100 outputs = 25 quads over 8 warps: warps 0-6 -> 3 quads, warp 7 -> 4.
template <int KA, int KB, int ACT>
__device__ __forceinline__ void gemm100T(
    const float* __restrict__ WT, const float* __restrict__ bias,
    const float* aA, const float* aB, float* out, int warp, int lane)
{
    if (warp < 7)
        gemmT<3, KA, KB, ACT>(WT + 12 * warp, bias, 12 * warp, aA, aB, out, lane);
    else
        gemmT<4, KA, KB, ACT>(WT + 84, bias, 84, aA, aB, out, lane);
}

// ---------------------------------------------------------------------------
// Heads fused: all four K=100->16 heads + softplus + KL + z, registers only.
// Warp w handles output pair o0 = 2w (8 warps cover Z=16).
__device__ __forceinline__ void heads_fused(
    const float* __restrict__ he, const float* __restrict__ hp,
    const float* __restrict__ bem, const float* __restrict__ bes,
    const float* __restrict__ bpm, const float* __restrict__ bps,
    const float* __restrict__ eps_t, int b0, float* __restrict__ zb,
    int warp, int lane, float& kl_acc)
{
    const int o0 = 2 * warp;
    const float* WemT = g_WT + O_Wemu + o0;
    const float* WesT = g_WT + O_Wesg + o0;
    const float* WpmT = g_WT + O_Wpmu + o0;
    const float* WpsT = g_WT + O_Wpsg + o0;
    ull EM[2] = {0, 0}, ES[2] = {0, 0}, PM[2] = {0, 0}, PS[2] = {0, 0};
    const ull* He = (const ull*)he;
    const ull* Hp = (const ull*)hp;
#pragma unroll 4
    for (int k = 0; k < 100; k++) {
        float2 e = unpk(He[k * 32 + lane]);
        float2 q = unpk(Hp[k * 32 + lane]);
        ull e0 = b2(e.x), e1 = b2(e.y), q0 = b2(q.x), q1 = b2(q.y);
        ull wem = *(const ull*)(WemT + k * 16);
        ull wes = *(const ull*)(WesT + k * 16);
        ull wpm = *(const ull*)(WpmT + k * 16);
        ull wps = *(const ull*)(WpsT + k * 16);
        EM[0] = fma2(wem, e0, EM[0]); EM[1] = fma2(wem, e1, EM[1]);
        ES[0] = fma2(wes, e0, ES[0]); ES[1] = fma2(wes, e1, ES[1]);
        PM[0] = fma2(wpm, q0, PM[0]); PM[1] = fma2(wpm, q1, PM[1]);
        PS[0] = fma2(wps, q0, PS[0]); PS[1] = fma2(wps, q1, PS[1]);
    }
    ull* z64 = (ull*)zb;
#pragma unroll
    for (int e = 0; e < 2; e++) {
        const int o = o0 + e;
        float zv[2];
#pragma unroll
        for (int r = 0; r < 2; r++) {
            float2 em = unpk(EM[r]), es = unpk(ES[r]);
            float2 pm = unpk(PM[r]), ps = unpk(PS[r]);
            float emu = (e ? em.y : em.x) + bem[o];
            float esg = act_apply((e ? es.y : es.x) + bes[o], ACT_SP);
            float pmu = (e ? pm.y : pm.x) + bpm[o];
            float psg = act_apply((e ? ps.y : ps.x) + bps[o], ACT_SP);
            float psx = psg + 1e-10f;
            float d   = emu - pmu;
            kl_acc += 0.5f * (2.f * logf(psx) - 2.f * logf(esg)
                              + (esg * esg + d * d) / (psx * psx) - 1.f);
            const int row = lane + 32 * r;
            float ev = eps_t[(size_t)row * Z_DIM + o];
            zv[r] = emu + sqrtf(esg) * ev;
        }
        z64[o * 32 + lane] = pk(zv[0], zv[1]);
    }
    (void)b0;
}

// ---------------------------------------------------------------------------
// GRU: task = 4 adjacent j's. Transposed Wih[200][300]/Whh[100][300];
// gate columns r at +0, u at +100, n at +200.
__device__ __forceinline__ void gru_segT(
    ull (&R)[2][2], ull (&U)[2][2], ull (&NX)[2][2],
    const float* __restrict__ Wk, const float* __restrict__ act, int lane)
{
    const ull* A = (const ull*)act;
#pragma unroll 4
    for (int k = 0; k < 100; k++) {
        float2 f = unpk(A[k * 32 + lane]);
        ull r0 = b2(f.x), r1 = b2(f.y);
        const float* w = Wk + (size_t)k * 300;
        ulonglong2 wr = *(const ulonglong2*)(w);
        ulonglong2 wu = *(const ulonglong2*)(w + 100);
        ulonglong2 wn = *(const ulonglong2*)(w + 200);
        R[0][0]  = fma2(wr.x, r0, R[0][0]);  R[0][1]  = fma2(wr.x, r1, R[0][1]);
        R[1][0]  = fma2(wr.y, r0, R[1][0]);  R[1][1]  = fma2(wr.y, r1, R[1][1]);
        U[0][0]  = fma2(wu.x, r0, U[0][0]);  U[0][1]  = fma2(wu.x, r1, U[0][1]);
        U[1][0]  = fma2(wu.y, r0, U[1][0]);  U[1][1]  = fma2(wu.y, r1, U[1][1]);
        NX[0][0] = fma2(wn.x, r0, NX[0][0]); NX[0][1] = fma2(wn.x, r1, NX[0][1]);
        NX[1][0] = fma2(wn.y, r0, NX[1][0]); NX[1][1] = fma2(wn.y, r1, NX[1][1]);
    }
}

__device__ __forceinline__ void gru_task(
    int j0, const float* __restrict__ bih, const float* __restrict__ bhh,
    const float* __restrict__ pz, const float* __restrict__ px,
    const float* __restrict__ hc, float* __restrict__ hn, int lane)
{
    ull R[2][2], U[2][2], NI[2][2], NH[2][2];
#pragma unroll
    for (int p = 0; p < 2; p++)
#pragma unroll
        for (int r = 0; r < 2; r++) { R[p][r]=0; U[p][r]=0; NI[p][r]=0; NH[p][r]=0; }

    gru_segT(R, U, NI, g_WT + O_Wih + j0,             pz, lane);
    gru_segT(R, U, NI, g_WT + O_Wih + 100 * 300 + j0, px, lane);
    gru_segT(R, U, NH, g_WT + O_Whh + j0,             hc, lane);

    const ull* h64 = (const ull*)hc;
    ull* n64 = (ull*)hn;
#pragma unroll
    for (int jj = 0; jj < 4; jj++) {
        const int p = jj >> 1, e = jj & 1, j = j0 + jj;
        const float br = bih[j] + bhh[j];
        const float bu = bih[100 + j] + bhh[100 + j];
        const float bn = bih[200 + j];
        const float bm = bhh[200 + j];
        float2 H = unpk(h64[j * 32 + lane]);
        float ov[2];
#pragma unroll
        for (int r = 0; r < 2; r++) {
            float2 Rv = unpk(R[p][r]), Uv = unpk(U[p][r]);
            float2 Nv = unpk(NI[p][r]), Mv = unpk(NH[p][r]);
            float rv = e ? Rv.y : Rv.x;
            float uv = e ? Uv.y : Uv.x;
            float nv = e ? Nv.y : Nv.x;
            float mv = e ? Mv.y : Mv.x;
            float rr = sigf(rv + br);
            float uu = sigf(uv + bu);
            float nn = tanhf(nv + bn + rr * (mv + bm));
            float hv = r ? H.y : H.x;
            ov[r] = (1.f - uu) * nn + uu * hv;
        }
        n64[j * 32 + lane] = pk(ov[0], ov[1]);
    }
}

// ---------------------------------------------------------------------------
// Wd3 (28 outputs) + fused Bernoulli NLL; warps 0-6, one quad each.
__device__ __forceinline__ void wd3_nll(
    const float* __restrict__ bd3, const float* __restrict__ hd2,
    const float* __restrict__ xs, int o0, int lane, float& nll)
{
    ull a0[2] = {0, 0}, a1[2] = {0, 0};
    const ull* A = (const ull*)hd2;
    const float* WT3 = g_WT + O_Wd3 + o0;
#pragma unroll 4
    for (int k = 0; k < 100; k++) {
        float2 f = unpk(A[k * 32 + lane]);
        ull r0 = b2(f.x), r1 = b2(f.y);
        ulonglong2 w = *(const ulonglong2*)(WT3 + k * 28);
        a0[0] = fma2(w.x, r0, a0[0]); a0[1] = fma2(w.y, r0, a0[1]);
        a1[0] = fma2(w.x, r1, a1[0]); a1[1] = fma2(w.y, r1, a1[1]);
    }
    const ull* X = (const ull*)xs;
#pragma unroll
    for (int p = 0; p < 2; p++) {
        float2 v0 = unpk(a0[p]);
        float2 v1 = unpk(a1[p]);
#pragma unroll
        for (int e = 0; e < 2; e++) {
            const int o = o0 + 2 * p + e;
            float p0 = sigf((e ? v0.y : v0.x) + bd3[o]);
            float p1 = sigf((e ? v1.y : v1.x) + bd3[o]);
            float2 xv = unpk(X[o * 32 + lane]);
            nll -= xv.x * logf(p0 + 1e-10f) + (1.f - xv.x) * logf(1.f - p0 + 1e-10f);
            nll -= xv.y * logf(p1 + 1e-10f) + (1.f - xv.y) * logf(1.f - p1 + 1e-10f);
        }
    }
}

// ---------------------------------------------------------------------------
__global__ void __launch_bounds__(NTHR, 2) vrnn_main(
    const float* __restrict__ x,      const float* __restrict__ eps,
    const float* __restrict__ bpx,    const float* __restrict__ bpz,
    const float* __restrict__ bp1,    const float* __restrict__ bp_mu,
    const float* __restrict__ bp_sig, const float* __restrict__ be1,
    const float* __restrict__ be_mu,  const float* __restrict__ be_sig,
    const float* __restrict__ bd1,    const float* __restrict__ bd2,
    const float* __restrict__ bd3,    const float* __restrict__ bih,
    const float* __restrict__ bhh,    float* __restrict__ out)
{
    extern __shared__ float s[];
    float* xs = s;                        // 28*64
    float* zb = xs + X_DIM * TB;          // 16*64
    float* H0 = zb + Z_DIM * TB;          // 4 x 100*64
    float* H1 = H0 + H_DIM * TB;
    float* H2 = H1 + H_DIM * TB;
    float* H3 = H2 + H_DIM * TB;

    __shared__ int s_last;

    const int tid  = threadIdx.x;
    const int lane = tid & 31;
    const int warp = tid >> 5;
    const int b0   = blockIdx.x * TB;

    float* hc  = H0;   // current h
    float* pxb = H1;   // px / hd1
    float* s1  = H2;   // he / pz
    float* s2  = H3;   // hp / hn

    for (int i = tid; i < H_DIM * TB; i += NTHR) hc[i] = 0.f;

    float kl_acc = 0.f, nll_acc = 0.f;

    for (int t = 0; t < T_STEPS; t++) {
        const float* xg  = x   + ((size_t)t * B_TOT + b0) * X_DIM;
        const float* ept = eps + ((size_t)t * B_TOT + b0) * Z_DIM;
        for (int i = tid; i < X_DIM * TB; i += NTHR) {
            int r = i / X_DIM, k = i % X_DIM;
            xs[(k * 32 + (r & 31)) * 2 + (r >> 5)] = xg[i];
        }
        __syncthreads();

        // 1. px = relu(Wpx x + b)
        gemm100T<28, 0, ACT_RELU>(g_WT + O_Wpx, bpx, xs, nullptr, pxb, warp, lane);
        __syncthreads();

        // 2+3. he = relu(We1 [px;h]) -> s1 ; hp = relu(Wp1 h) -> s2
        gemm100T<100, 100, ACT_RELU>(g_WT + O_We1, be1, pxb, hc, s1, warp, lane);
        gemm100T<100, 0,   ACT_RELU>(g_WT + O_Wp1, bp1, hc, nullptr, s2, warp, lane);
        __syncthreads();

        // 4. heads + KL + z (registers only)
        heads_fused(s1, s2, be_mu, be_sig, bp_mu, bp_sig, ept, b0, zb,
                    warp, lane, kl_acc);
        __syncthreads();

        // 5. pz = relu(Wpz z + b) -> s1
        gemm100T<16, 0, ACT_RELU>(g_WT + O_Wpz, bpz, zb, nullptr, s1, warp, lane);
        __syncthreads();

        // 6. GRU(pz, px, h) -> hn into s2
        for (int t4 = warp; t4 < 25; t4 += 8)
            gru_task(4 * t4, bih, bhh, s1, pxb, hc, s2, lane);
        __syncthreads();

        // 7. hd1 = relu(Wd1 [pz;h]) -> pxb (px dead after GRU)
        gemm100T<100, 100, ACT_RELU>(g_WT + O_Wd1, bd1, s1, hc, pxb, warp, lane);
        __syncthreads();

        // 8. hd2 = relu(Wd2 hd1) -> hc buffer (h dead after stage 7)
        gemm100T<100, 0, ACT_RELU>(g_WT + O_Wd2, bd2, pxb, nullptr, hc, warp, lane);
        __syncthreads();

        // 9. Wd3 + fused NLL (warps 0-6)
        if (warp < 7)
            wd3_nll(bd3, hc, xs, 4 * warp, lane, nll_acc);

        // rotate: new h = hn (s2); old hc buffer becomes scratch
        { float* tmp = hc; hc = s2; s2 = tmp; }
        __syncthreads();
    }

    // ---- block partial reduction (8 warps)
#pragma unroll
    for (int off = 16; off > 0; off >>= 1) {
        kl_acc  += __shfl_down_sync(0xffffffffu, kl_acc,  off);
        nll_acc += __shfl_down_sync(0xffffffffu, nll_acc, off);
    }
    if (lane == 0) { s[warp] = kl_acc; s[8 + warp] = nll_acc; }
    __syncthreads();
    if (tid == 0) {
        float k = 0.f, n = 0.f;
        for (int w = 0; w < 8; w++) { k += s[w]; n += s[8 + w]; }
        g_part[2 * blockIdx.x + 0] = k;
        g_part[2 * blockIdx.x + 1] = n;
        __threadfence();
        unsigned v = atomicAdd(&g_done, 1u);
        s_last = (v == (unsigned)(gridDim.x - 1)) ? 1 : 0;
    }
    __syncthreads();

    // ---- deterministic final reduction in the last-arriving block
    if (s_last) {
        s[tid]       = g_part[2 * tid + 0];   // NBLK == NTHR == 256
        s[256 + tid] = g_part[2 * tid + 1];
        __syncthreads();
        for (int st = 128; st > 0; st >>= 1) {
            if (tid < st) { s[tid] += s[tid + st]; s[256 + tid] += s[256 + tid + st]; }
            __syncthreads();
        }
        if (tid == 0) {
            const float invB = 1.f / (float)B_TOT;
            out[0] = s[0] * invB;
            out[1] = s[256] * invB;
            g_done = 0;                  // reset for next graph replay
        }
    }
}

// ---------------------------------------------------------------------------
extern "C" void kernel_launch(void* const* d_in, const int* in_sizes, int n_in,
                              void* d_out, int out_size)
{
    (void)in_sizes; (void)n_in; (void)out_size;
    const float* x      = (const float*)d_in[0];
    const float* eps    = (const float*)d_in[1];
    const float* Wpx    = (const float*)d_in[2];
    const float* bpx    = (const float*)d_in[3];
    const float* Wpz    = (const float*)d_in[4];
    const float* bpz    = (const float*)d_in[5];
    const float* Wp1    = (const float*)d_in[6];
    const float* bp1    = (const float*)d_in[7];
    const float* Wp_mu  = (const float*)d_in[8];
    const float* bp_mu  = (const float*)d_in[9];
    const float* Wp_sig = (const float*)d_in[10];
    const float* bp_sig = (const float*)d_in[11];
    const float* We1    = (const float*)d_in[12];
    const float* be1    = (const float*)d_in[13];
    const float* We_mu  = (const float*)d_in[14];
    const float* be_mu  = (const float*)d_in[15];
    const float* We_sig = (const float*)d_in[16];
    const float* be_sig = (const float*)d_in[17];
    const float* Wd1    = (const float*)d_in[18];
    const float* bd1    = (const float*)d_in[19];
    const float* Wd2    = (const float*)d_in[20];
    const float* bd2    = (const float*)d_in[21];
    const float* Wd3    = (const float*)d_in[22];
    const float* bd3    = (const float*)d_in[23];
    const float* Wih    = (const float*)d_in[24];
    const float* Whh    = (const float*)d_in[25];
    const float* bih    = (const float*)d_in[26];
    const float* bhh    = (const float*)d_in[27];
    float* out = (float*)d_out;

    prep_transpose<<<160, 256>>>(Wpx, Wpz, Wp1, Wp_mu, Wp_sig, We_mu, We_sig,
                                 We1, Wd1, Wd2, Wd3, Wih, Whh);

    const int smem_floats = X_DIM * TB + Z_DIM * TB + 4 * H_DIM * TB;  // 28,416
    const int smem_bytes  = smem_floats * (int)sizeof(float);          // 113,664

    cudaFuncSetAttribute(vrnn_main,
                         cudaFuncAttributeMaxDynamicSharedMemorySize, smem_bytes);

    vrnn_main<<<NBLK, NTHR, smem_bytes>>>(
        x, eps, bpx, bpz, bp1, bp_mu, bp_sig, be1, be_mu, be_sig,
        bd1, bd2, bd3, bih, bhh, out);
}

// round 11
// speedup vs baseline: 1.0047x; 1.0021x over previous
#include <cuda_runtime.h>
#include <math.h>

using ull = unsigned long long;

constexpr int T_STEPS = 28;
constexpr int B_TOT   = 16384;
constexpr int X_DIM   = 28;
constexpr int H_DIM   = 100;
constexpr int Z_DIM   = 16;
constexpr int TB      = 64;              // batch rows per block (2 per lane)
constexpr int NBLK    = B_TOT / TB;      // 256 blocks, 2 per SM -> one wave
constexpr int NTHR    = 256;             // 8 warps

// Transposed weights (654,400 B) + reduction state
__device__ float        g_WT[163600];
__device__ float        g_part[NBLK * 2];
__device__ unsigned int g_done;

// WT segment offsets (floats): WT[off + k*N + o] = W[o*K + k]
constexpr int O_Wpx  = 0;       // N=100 K=28
constexpr int O_Wpz  = 2800;    // N=100 K=16
constexpr int O_Wp1  = 4400;    // N=100 K=100
constexpr int O_Wpmu = 14400;   // N=16  K=100
constexpr int O_Wpsg = 16000;
constexpr int O_Wemu = 17600;
constexpr int O_Wesg = 19200;
constexpr int O_We1  = 20800;   // N=100 K=200
constexpr int O_Wd1  = 40800;   // N=100 K=200
constexpr int O_Wd2  = 60800;   // N=100 K=100
constexpr int O_Wd3  = 70800;   // N=28  K=100
constexpr int O_Wih  = 73600;   // N=300 K=200
constexpr int O_Whh  = 133600;  // N=300 K=100

enum { ACT_LIN = 0, ACT_RELU = 1, ACT_SIG = 2, ACT_SP = 3 };

__device__ __forceinline__ float act_apply(float v, int A) {
    if (A == ACT_RELU) return fmaxf(v, 0.f);
    if (A == ACT_SIG)  return 1.f / (1.f + expf(-v));
    if (A == ACT_SP)   return fmaxf(v, 0.f) + log1pf(expf(-fabsf(v)));
    return v;
}
__device__ __forceinline__ float sigf(float v) { return 1.f / (1.f + expf(-v)); }

__device__ __forceinline__ ull b2(float v) {
    ull r; asm("mov.b64 %0,{%1,%1};" : "=l"(r) : "f"(v)); return r;
}
__device__ __forceinline__ ull fma2(ull a, ull b, ull c) {
    ull d; asm("fma.rn.f32x2 %0,%1,%2,%3;" : "=l"(d) : "l"(a), "l"(b), "l"(c));
    return d;
}
__device__ __forceinline__ float2 unpk(ull v) {
    float2 f; asm("mov.b64 {%0,%1},%2;" : "=f"(f.x), "=f"(f.y) : "l"(v)); return f;
}
__device__ __forceinline__ ull pk(float x, float y) {
    ull r; asm("mov.b64 %0,{%1,%2};" : "=l"(r) : "f"(x), "f"(y)); return r;
}

// ---------------------------------------------------------------------------
// Prep: transpose all weight matrices into g_WT (cheap, graph-capturable).
__global__ void prep_transpose(
    const float* __restrict__ Wpx, const float* __restrict__ Wpz,
    const float* __restrict__ Wp1, const float* __restrict__ Wpmu,
    const float* __restrict__ Wpsg, const float* __restrict__ Wemu,
    const float* __restrict__ Wesg, const float* __restrict__ We1,
    const float* __restrict__ Wd1, const float* __restrict__ Wd2,
    const float* __restrict__ Wd3, const float* __restrict__ Wih,
    const float* __restrict__ Whh)
{
    for (int idx = blockIdx.x * blockDim.x + threadIdx.x; idx < 163600;
         idx += gridDim.x * blockDim.x) {
        const float* W; int N, K, off;
        if      (idx < O_Wpz ) { W = Wpx;  N = 100; K = 28;  off = O_Wpx;  }
        else if (idx < O_Wp1 ) { W = Wpz;  N = 100; K = 16;  off = O_Wpz;  }
        else if (idx < O_Wpmu) { W = Wp1;  N = 100; K = 100; off = O_Wp1;  }
        else if (idx < O_Wpsg) { W = Wpmu; N = 16;  K = 100; off = O_Wpmu; }
        else if (idx < O_Wemu) { W = Wpsg; N = 16;  K = 100; off = O_Wpsg; }
        else if (idx < O_Wesg) { W = Wemu; N = 16;  K = 100; off = O_Wemu; }
        else if (idx < O_We1 ) { W = Wesg; N = 16;  K = 100; off = O_Wesg; }
        else if (idx < O_Wd1 ) { W = We1;  N = 100; K = 200; off = O_We1;  }
        else if (idx < O_Wd2 ) { W = Wd1;  N = 100; K = 200; off = O_Wd1;  }
        else if (idx < O_Wd3 ) { W = Wd2;  N = 100; K = 100; off = O_Wd2;  }
        else if (idx < O_Wih ) { W = Wd3;  N = 28;  K = 100; off = O_Wd3;  }
        else if (idx < O_Whh ) { W = Wih;  N = 300; K = 200; off = O_Wih;  }
        else                   { W = Whh;  N = 300; K = 100; off = O_Whh;  }
        int l = idx - off;
        int k = l / N, o = l % N;
        g_WT[idx] = W[o * K + k];
    }
}

// ---------------------------------------------------------------------------
// gemmT: NQ quads (4 outputs each) with transposed weights.
// Activations feat-major packed: act_u64[k*32+lane] = rows (lane, lane+32).
// WTo pre-offset by o0 (column); o0 must be multiple of 4 (16B alignment).
template <int NQ, int KA, int KB, int ACT>
__device__ __forceinline__ void gemmT(
    const float* __restrict__ WTo, const float* __restrict__ bias, int o0,
    const float* __restrict__ actA, const float* __restrict__ actB,
    float* __restrict__ out, int lane)
{
    ull a0[2 * NQ], a1[2 * NQ];     // [pair]: rows lane / lane+32
#pragma unroll
    for (int i = 0; i < 2 * NQ; i++) { a0[i] = 0ull; a1[i] = 0ull; }

    {
        const ull* A = (const ull*)actA;
#pragma unroll 4
        for (int k = 0; k < KA; k++) {
            float2 f = unpk(A[k * 32 + lane]);
            ull r0 = b2(f.x), r1 = b2(f.y);
#pragma unroll
            for (int q = 0; q < NQ; q++) {
                ulonglong2 w = *(const ulonglong2*)(WTo + (size_t)k * 100 + 4 * q);
                a0[2*q]   = fma2(w.x, r0, a0[2*q]);
                a0[2*q+1] = fma2(w.y, r0, a0[2*q+1]);
                a1[2*q]   = fma2(w.x, r1, a1[2*q]);
                a1[2*q+1] = fma2(w.y, r1, a1[2*q+1]);
            }
        }
    }
    if constexpr (KB > 0) {
        const ull* A = (const ull*)actB;
#pragma unroll 4
        for (int k = 0; k < KB; k++) {
            float2 f = unpk(A[k * 32 + lane]);
            ull r0 = b2(f.x), r1 = b2(f.y);
#pragma unroll
            for (int q = 0; q < NQ; q++) {
                ulonglong2 w = *(const ulonglong2*)(WTo + (size_t)(KA + k) * 100 + 4 * q);
                a0[2*q]   = fma2(w.x, r0, a0[2*q]);
                a0[2*q+1] = fma2(w.y, r0, a0[2*q+1]);
                a1[2*q]   = fma2(w.x, r1, a1[2*q]);
                a1[2*q+1] = fma2(w.y, r1, a1[2*q+1]);
            }
        }
    }
    ull* o64 = (ull*)out;
#pragma unroll
    for (int p = 0; p < 2 * NQ; p++) {
        const int o = o0 + 2 * p;
        float2 v0 = unpk(a0[p]);     // outputs (o, o+1), row lane
        float2 v1 = unpk(a1[p]);     // row lane+32
        o64[o * 32 + lane]       = pk(act_apply(v0.x + bias[o], ACT),
                                      act_apply(v1.x + bias[o], ACT));
        o64[(o + 1) * 32 + lane] = pk(act_apply(v0.y + bias[o + 1], ACT),
                                      act_apply(v1.y + bias[o + 1], ACT));
    }
}

// 100 outputs = 25 quads over 8 warps: warps 0-6 -> 3 quads, warp 7 -> 4.
template <int KA, int KB, int ACT>
__device__ __forceinline__ void gemm100T(
    const float* __restrict__ WT, const float* __restrict__ bias,
    const float* aA, const float* aB, float* out, int warp, int lane)
{
    if (warp < 7)
        gemmT<3, KA, KB, ACT>(WT + 12 * warp, bias, 12 * warp, aA, aB, out, lane);
    else
        gemmT<4, KA, KB, ACT>(WT + 84, bias, 84, aA, aB, out, lane);
}

// ---------------------------------------------------------------------------
// Heads fused: all four K=100->16 heads + softplus + KL + z, registers only.
// Warp w handles output pair o0 = 2w (8 warps cover Z=16).
__device__ __forceinline__ void heads_fused(
    const float* __restrict__ he, const float* __restrict__ hp,
    const float* __restrict__ bem, const float* __restrict__ bes,
    const float* __restrict__ bpm, const float* __restrict__ bps,
    const float* __restrict__ eps_t, int b0, float* __restrict__ zb,
    int warp, int lane, float& kl_acc)
{
    const int o0 = 2 * warp;
    const float* WemT = g_WT + O_Wemu + o0;
    const float* WesT = g_WT + O_Wesg + o0;
    const float* WpmT = g_WT + O_Wpmu + o0;
    const float* WpsT = g_WT + O_Wpsg + o0;
    ull EM[2] = {0, 0}, ES[2] = {0, 0}, PM[2] = {0, 0}, PS[2] = {0, 0};
    const ull* He = (const ull*)he;
    const ull* Hp = (const ull*)hp;
#pragma unroll 4
    for (int k = 0; k < 100; k++) {
        float2 e = unpk(He[k * 32 + lane]);
        float2 q = unpk(Hp[k * 32 + lane]);
        ull e0 = b2(e.x), e1 = b2(e.y), q0 = b2(q.x), q1 = b2(q.y);
        ull wem = *(const ull*)(WemT + k * 16);
        ull wes = *(const ull*)(WesT + k * 16);
        ull wpm = *(const ull*)(WpmT + k * 16);
        ull wps = *(const ull*)(WpsT + k * 16);
        EM[0] = fma2(wem, e0, EM[0]); EM[1] = fma2(wem, e1, EM[1]);
        ES[0] = fma2(wes, e0, ES[0]); ES[1] = fma2(wes, e1, ES[1]);
        PM[0] = fma2(wpm, q0, PM[0]); PM[1] = fma2(wpm, q1, PM[1]);
        PS[0] = fma2(wps, q0, PS[0]); PS[1] = fma2(wps, q1, PS[1]);
    }
    ull* z64 = (ull*)zb;
#pragma unroll
    for (int e = 0; e < 2; e++) {
        const int o = o0 + e;
        float zv[2];
#pragma unroll
        for (int r = 0; r < 2; r++) {
            float2 em = unpk(EM[r]), es = unpk(ES[r]);
            float2 pm = unpk(PM[r]), ps = unpk(PS[r]);
            float emu = (e ? em.y : em.x) + bem[o];
            float esg = act_apply((e ? es.y : es.x) + bes[o], ACT_SP);
            float pmu = (e ? pm.y : pm.x) + bpm[o];
            float psg = act_apply((e ? ps.y : ps.x) + bps[o], ACT_SP);
            float psx = psg + 1e-10f;
            float d   = emu - pmu;
            kl_acc += 0.5f * (2.f * logf(psx) - 2.f * logf(esg)
                              + (esg * esg + d * d) / (psx * psx) - 1.f);
            const int row = lane + 32 * r;
            float ev = eps_t[(size_t)row * Z_DIM + o];
            zv[r] = emu + sqrtf(esg) * ev;
        }
        z64[o * 32 + lane] = pk(zv[0], zv[1]);
    }
    (void)b0;
}

// ---------------------------------------------------------------------------
// GRU: task = 4 adjacent j's. Transposed Wih[200][300]/Whh[100][300];
// gate columns r at +0, u at +100, n at +200.
__device__ __forceinline__ void gru_segT(
    ull (&R)[2][2], ull (&U)[2][2], ull (&NX)[2][2],
    const float* __restrict__ Wk, const float* __restrict__ act, int lane)
{
    const ull* A = (const ull*)act;
#pragma unroll 4
    for (int k = 0; k < 100; k++) {
        float2 f = unpk(A[k * 32 + lane]);
        ull r0 = b2(f.x), r1 = b2(f.y);
        const float* w = Wk + (size_t)k * 300;
        ulonglong2 wr = *(const ulonglong2*)(w);
        ulonglong2 wu = *(const ulonglong2*)(w + 100);
        ulonglong2 wn = *(const ulonglong2*)(w + 200);
        R[0][0]  = fma2(wr.x, r0, R[0][0]);  R[0][1]  = fma2(wr.x, r1, R[0][1]);
        R[1][0]  = fma2(wr.y, r0, R[1][0]);  R[1][1]  = fma2(wr.y, r1, R[1][1]);
        U[0][0]  = fma2(wu.x, r0, U[0][0]);  U[0][1]  = fma2(wu.x, r1, U[0][1]);
        U[1][0]  = fma2(wu.y, r0, U[1][0]);  U[1][1]  = fma2(wu.y, r1, U[1][1]);
        NX[0][0] = fma2(wn.x, r0, NX[0][0]); NX[0][1] = fma2(wn.x, r1, NX[0][1]);
        NX[1][0] = fma2(wn.y, r0, NX[1][0]); NX[1][1] = fma2(wn.y, r1, NX[1][1]);
    }
}

__device__ __forceinline__ void gru_task(
    int j0, const float* __restrict__ bih, const float* __restrict__ bhh,
    const float* __restrict__ pz, const float* __restrict__ px,
    const float* __restrict__ hc, float* __restrict__ hn, int lane)
{
    ull R[2][2], U[2][2], NI[2][2], NH[2][2];
#pragma unroll
    for (int p = 0; p < 2; p++)
#pragma unroll
        for (int r = 0; r < 2; r++) { R[p][r]=0; U[p][r]=0; NI[p][r]=0; NH[p][r]=0; }

    gru_segT(R, U, NI, g_WT + O_Wih + j0,             pz, lane);
    gru_segT(R, U, NI, g_WT + O_Wih + 100 * 300 + j0, px, lane);
    gru_segT(R, U, NH, g_WT + O_Whh + j0,             hc, lane);

    const ull* h64 = (const ull*)hc;
    ull* n64 = (ull*)hn;
#pragma unroll
    for (int jj = 0; jj < 4; jj++) {
        const int p = jj >> 1, e = jj & 1, j = j0 + jj;
        const float br = bih[j] + bhh[j];
        const float bu = bih[100 + j] + bhh[100 + j];
        const float bn = bih[200 + j];
        const float bm = bhh[200 + j];
        float2 H = unpk(h64[j * 32 + lane]);
        float ov[2];
#pragma unroll
        for (int r = 0; r < 2; r++) {
            float2 Rv = unpk(R[p][r]), Uv = unpk(U[p][r]);
            float2 Nv = unpk(NI[p][r]), Mv = unpk(NH[p][r]);
            float rv = e ? Rv.y : Rv.x;
            float uv = e ? Uv.y : Uv.x;
            float nv = e ? Nv.y : Nv.x;
            float mv = e ? Mv.y : Mv.x;
            float rr = sigf(rv + br);
            float uu = sigf(uv + bu);
            float nn = tanhf(nv + bn + rr * (mv + bm));
            float hv = r ? H.y : H.x;
            ov[r] = (1.f - uu) * nn + uu * hv;
        }
        n64[j * 32 + lane] = pk(ov[0], ov[1]);
    }
}

// ---------------------------------------------------------------------------
// Wd3 (28 outputs) + fused Bernoulli NLL; warps 0-6, one quad each.
__device__ __forceinline__ void wd3_nll(
    const float* __restrict__ bd3, const float* __restrict__ hd2,
    const float* __restrict__ xs, int o0, int lane, float& nll)
{
    ull a0[2] = {0, 0}, a1[2] = {0, 0};
    const ull* A = (const ull*)hd2;
    const float* WT3 = g_WT + O_Wd3 + o0;
#pragma unroll 4
    for (int k = 0; k < 100; k++) {
        float2 f = unpk(A[k * 32 + lane]);
        ull r0 = b2(f.x), r1 = b2(f.y);
        ulonglong2 w = *(const ulonglong2*)(WT3 + k * 28);
        a0[0] = fma2(w.x, r0, a0[0]); a0[1] = fma2(w.y, r0, a0[1]);
        a1[0] = fma2(w.x, r1, a1[0]); a1[1] = fma2(w.y, r1, a1[1]);
    }
    const ull* X = (const ull*)xs;
#pragma unroll
    for (int p = 0; p < 2; p++) {
        float2 v0 = unpk(a0[p]);
        float2 v1 = unpk(a1[p]);
#pragma unroll
        for (int e = 0; e < 2; e++) {
            const int o = o0 + 2 * p + e;
            float p0 = sigf((e ? v0.y : v0.x) + bd3[o]);
            float p1 = sigf((e ? v1.y : v1.x) + bd3[o]);
            float2 xv = unpk(X[o * 32 + lane]);
            nll -= xv.x * logf(p0 + 1e-10f) + (1.f - xv.x) * logf(1.f - p0 + 1e-10f);
            nll -= xv.y * logf(p1 + 1e-10f) + (1.f - xv.y) * logf(1.f - p1 + 1e-10f);
        }
    }
}

// ---------------------------------------------------------------------------
__global__ void __launch_bounds__(NTHR, 2) vrnn_main(
    const float* __restrict__ x,      const float* __restrict__ eps,
    const float* __restrict__ bpx,    const float* __restrict__ bpz,
    const float* __restrict__ bp1,    const float* __restrict__ bp_mu,
    const float* __restrict__ bp_sig, const float* __restrict__ be1,
    const float* __restrict__ be_mu,  const float* __restrict__ be_sig,
    const float* __restrict__ bd1,    const float* __restrict__ bd2,
    const float* __restrict__ bd3,    const float* __restrict__ bih,
    const float* __restrict__ bhh,    float* __restrict__ out)
{
    extern __shared__ float s[];
    float* xs = s;                        // 28*64
    float* zb = xs + X_DIM * TB;          // 16*64
    float* H0 = zb + Z_DIM * TB;          // 4 x 100*64
    float* H1 = H0 + H_DIM * TB;
    float* H2 = H1 + H_DIM * TB;
    float* H3 = H2 + H_DIM * TB;

    __shared__ int s_last;

    const int tid  = threadIdx.x;
    const int lane = tid & 31;
    const int warp = tid >> 5;
    const int b0   = blockIdx.x * TB;

    float* hc  = H0;   // current h
    float* pxb = H1;   // px / hd1
    float* s1  = H2;   // he / pz
    float* s2  = H3;   // hp / hn

    for (int i = tid; i < H_DIM * TB; i += NTHR) hc[i] = 0.f;

    float kl_acc = 0.f, nll_acc = 0.f;

    for (int t = 0; t < T_STEPS; t++) {
        const float* xg  = x   + ((size_t)t * B_TOT + b0) * X_DIM;
        const float* ept = eps + ((size_t)t * B_TOT + b0) * Z_DIM;
        for (int i = tid; i < X_DIM * TB; i += NTHR) {
            int r = i / X_DIM, k = i % X_DIM;
            xs[(k * 32 + (r & 31)) * 2 + (r >> 5)] = xg[i];
        }
        __syncthreads();

        // 1. px = relu(Wpx x + b)
        gemm100T<28, 0, ACT_RELU>(g_WT + O_Wpx, bpx, xs, nullptr, pxb, warp, lane);
        __syncthreads();

        // 2+3. he = relu(We1 [px;h]) -> s1 ; hp = relu(Wp1 h) -> s2
        gemm100T<100, 100, ACT_RELU>(g_WT + O_We1, be1, pxb, hc, s1, warp, lane);
        gemm100T<100, 0,   ACT_RELU>(g_WT + O_Wp1, bp1, hc, nullptr, s2, warp, lane);
        __syncthreads();

        // 4. heads + KL + z (registers only)
        heads_fused(s1, s2, be_mu, be_sig, bp_mu, bp_sig, ept, b0, zb,
                    warp, lane, kl_acc);
        __syncthreads();

        // 5. pz = relu(Wpz z + b) -> s1
        gemm100T<16, 0, ACT_RELU>(g_WT + O_Wpz, bpz, zb, nullptr, s1, warp, lane);
        __syncthreads();

        // 6. GRU(pz, px, h) -> hn into s2
        for (int t4 = warp; t4 < 25; t4 += 8)
            gru_task(4 * t4, bih, bhh, s1, pxb, hc, s2, lane);
        __syncthreads();

        // 7. hd1 = relu(Wd1 [pz;h]) -> pxb (px dead after GRU)
        gemm100T<100, 100, ACT_RELU>(g_WT + O_Wd1, bd1, s1, hc, pxb, warp, lane);
        __syncthreads();

        // 8. hd2 = relu(Wd2 hd1) -> hc buffer (h dead after stage 7)
        gemm100T<100, 0, ACT_RELU>(g_WT + O_Wd2, bd2, pxb, nullptr, hc, warp, lane);
        __syncthreads();

        // 9. Wd3 + fused NLL (warps 0-6)
        if (warp < 7)
            wd3_nll(bd3, hc, xs, 4 * warp, lane, nll_acc);

        // rotate: new h = hn (s2); old hc buffer becomes scratch
        { float* tmp = hc; hc = s2; s2 = tmp; }
        __syncthreads();
    }

    // ---- block partial reduction (8 warps)
#pragma unroll
    for (int off = 16; off > 0; off >>= 1) {
        kl_acc  += __shfl_down_sync(0xffffffffu, kl_acc,  off);
        nll_acc += __shfl_down_sync(0xffffffffu, nll_acc, off);
    }
    if (lane == 0) { s[warp] = kl_acc; s[8 + warp] = nll_acc; }
    __syncthreads();
    if (tid == 0) {
        float k = 0.f, n = 0.f;
        for (int w = 0; w < 8; w++) { k += s[w]; n += s[8 + w]; }
        g_part[2 * blockIdx.x + 0] = k;
        g_part[2 * blockIdx.x + 1] = n;
        __threadfence();
        unsigned v = atomicAdd(&g_done, 1u);
        s_last = (v == (unsigned)(gridDim.x - 1)) ? 1 : 0;
    }
    __syncthreads();

    // ---- deterministic final reduction in the last-arriving block
    if (s_last) {
        s[tid]       = g_part[2 * tid + 0];   // NBLK == NTHR == 256
        s[256 + tid] = g_part[2 * tid + 1];
        __syncthreads();
        for (int st = 128; st > 0; st >>= 1) {
            if (tid < st) { s[tid] += s[tid + st]; s[256 + tid] += s[256 + tid + st]; }
            __syncthreads();
        }
        if (tid == 0) {
            const float invB = 1.f / (float)B_TOT;
            out[0] = s[0] * invB;
            out[1] = s[256] * invB;
            g_done = 0;                  // reset for next graph replay
        }
    }
}

// ---------------------------------------------------------------------------
extern "C" void kernel_launch(void* const* d_in, const int* in_sizes, int n_in,
                              void* d_out, int out_size)
{
    (void)in_sizes; (void)n_in; (void)out_size;
    const float* x      = (const float*)d_in[0];
    const float* eps    = (const float*)d_in[1];
    const float* Wpx    = (const float*)d_in[2];
    const float* bpx    = (const float*)d_in[3];
    const float* Wpz    = (const float*)d_in[4];
    const float* bpz    = (const float*)d_in[5];
    const float* Wp1    = (const float*)d_in[6];
    const float* bp1    = (const float*)d_in[7];
    const float* Wp_mu  = (const float*)d_in[8];
    const float* bp_mu  = (const float*)d_in[9];
    const float* Wp_sig = (const float*)d_in[10];
    const float* bp_sig = (const float*)d_in[11];
    const float* We1    = (const float*)d_in[12];
    const float* be1    = (const float*)d_in[13];
    const float* We_mu  = (const float*)d_in[14];
    const float* be_mu  = (const float*)d_in[15];
    const float* We_sig = (const float*)d_in[16];
    const float* be_sig = (const float*)d_in[17];
    const float* Wd1    = (const float*)d_in[18];
    const float* bd1    = (const float*)d_in[19];
    const float* Wd2    = (const float*)d_in[20];
    const float* bd2    = (const float*)d_in[21];
    const float* Wd3    = (const float*)d_in[22];
    const float* bd3    = (const float*)d_in[23];
    const float* Wih    = (const float*)d_in[24];
    const float* Whh    = (const float*)d_in[25];
    const float* bih    = (const float*)d_in[26];
    const float* bhh    = (const float*)d_in[27];
    float* out = (float*)d_out;

    prep_transpose<<<160, 256>>>(Wpx, Wpz, Wp1, Wp_mu, Wp_sig, We_mu, We_sig,
                                 We1, Wd1, Wd2, Wd3, Wih, Whh);

    const int smem_floats = X_DIM * TB + Z_DIM * TB + 4 * H_DIM * TB;  // 28,416
    const int smem_bytes  = smem_floats * (int)sizeof(float);          // 113,664

    cudaFuncSetAttribute(vrnn_main,
                         cudaFuncAttributeMaxDynamicSharedMemorySize, smem_bytes);

    vrnn_main<<<NBLK, NTHR, smem_bytes>>>(
        x, eps, bpx, bpz, bp1, bp_mu, bp_sig, be1, be_mu, be_sig,
        bd1, bd2, bd3, bih, bhh, out);
}

// round 12
// speedup vs baseline: 1.4514x; 1.4447x over previous
#include <cuda_runtime.h>
#include <math.h>

using ull = unsigned long long;

constexpr int T_STEPS = 28;
constexpr int B_TOT   = 16384;
constexpr int X_DIM   = 28;
constexpr int H_DIM   = 100;
constexpr int Z_DIM   = 16;
constexpr int TB      = 128;             // batch rows per block (4 per lane)
constexpr int NBLK    = B_TOT / TB;      // 128 blocks -> single wave
constexpr int NTHR    = 512;             // 16 warps

// Transposed weights (654,400 B) + reduction state
__device__ float        g_WT[163600];
__device__ float        g_part[NBLK * 2];
__device__ unsigned int g_done;

// WT segment offsets (floats): WT[off + k*N + o] = W[o*K + k]
constexpr int O_Wpx  = 0;       // N=100 K=28
constexpr int O_Wpz  = 2800;    // N=100 K=16
constexpr int O_Wp1  = 4400;    // N=100 K=100
constexpr int O_Wpmu = 14400;   // N=16  K=100
constexpr int O_Wpsg = 16000;
constexpr int O_Wemu = 17600;
constexpr int O_Wesg = 19200;
constexpr int O_We1  = 20800;   // N=100 K=200
constexpr int O_Wd1  = 40800;   // N=100 K=200
constexpr int O_Wd2  = 60800;   // N=100 K=100
constexpr int O_Wd3  = 70800;   // N=28  K=100
constexpr int O_Wih  = 73600;   // N=300 K=200
constexpr int O_Whh  = 133600;  // N=300 K=100

enum { ACT_LIN = 0, ACT_RELU = 1, ACT_SIG = 2, ACT_SP = 3 };

__device__ __forceinline__ float act_apply(float v, int A) {
    if (A == ACT_RELU) return fmaxf(v, 0.f);
    if (A == ACT_SIG)  return 1.f / (1.f + expf(-v));
    if (A == ACT_SP)   return fmaxf(v, 0.f) + log1pf(expf(-fabsf(v)));
    return v;
}
__device__ __forceinline__ float sigf(float v) { return 1.f / (1.f + expf(-v)); }

__device__ __forceinline__ ull b2(float v) {
    ull r; asm("mov.b64 %0,{%1,%1};" : "=l"(r) : "f"(v)); return r;
}
__device__ __forceinline__ ull fma2(ull a, ull b, ull c) {
    ull d; asm("fma.rn.f32x2 %0,%1,%2,%3;" : "=l"(d) : "l"(a), "l"(b), "l"(c));
    return d;
}
__device__ __forceinline__ float2 unpk(ull v) {
    float2 f; asm("mov.b64 {%0,%1},%2;" : "=f"(f.x), "=f"(f.y) : "l"(v)); return f;
}
__device__ __forceinline__ ull pk(float x, float y) {
    ull r; asm("mov.b64 %0,{%1,%2};" : "=l"(r) : "f"(x), "f"(y)); return r;
}

// ---------------------------------------------------------------------------
__global__ void prep_transpose(
    const float* __restrict__ Wpx, const float* __restrict__ Wpz,
    const float* __restrict__ Wp1, const float* __restrict__ Wpmu,
    const float* __restrict__ Wpsg, const float* __restrict__ Wemu,
    const float* __restrict__ Wesg, const float* __restrict__ We1,
    const float* __restrict__ Wd1, const float* __restrict__ Wd2,
    const float* __restrict__ Wd3, const float* __restrict__ Wih,
    const float* __restrict__ Whh)
{
    for (int idx = blockIdx.x * blockDim.x + threadIdx.x; idx < 163600;
         idx += gridDim.x * blockDim.x) {
        const float* W; int N, K, off;
        if      (idx < O_Wpz ) { W = Wpx;  N = 100; K = 28;  off = O_Wpx;  }
        else if (idx < O_Wp1 ) { W = Wpz;  N = 100; K = 16;  off = O_Wpz;  }
        else if (idx < O_Wpmu) { W = Wp1;  N = 100; K = 100; off = O_Wp1;  }
        else if (idx < O_Wpsg) { W = Wpmu; N = 16;  K = 100; off = O_Wpmu; }
        else if (idx < O_Wemu) { W = Wpsg; N = 16;  K = 100; off = O_Wpsg; }
        else if (idx < O_Wesg) { W = Wemu; N = 16;  K = 100; off = O_Wemu; }
        else if (idx < O_We1 ) { W = Wesg; N = 16;  K = 100; off = O_Wesg; }
        else if (idx < O_Wd1 ) { W = We1;  N = 100; K = 200; off = O_We1;  }
        else if (idx < O_Wd2 ) { W = Wd1;  N = 100; K = 200; off = O_Wd1;  }
        else if (idx < O_Wd3 ) { W = Wd2;  N = 100; K = 100; off = O_Wd2;  }
        else if (idx < O_Wih ) { W = Wd3;  N = 28;  K = 100; off = O_Wd3;  }
        else if (idx < O_Whh ) { W = Wih;  N = 300; K = 200; off = O_Wih;  }
        else                   { W = Whh;  N = 300; K = 100; off = O_Whh;  }
        int l = idx - off;
        int k = l / N, o = l % N;
        g_WT[idx] = W[o * K + k];
    }
}

// ---------------------------------------------------------------------------
// Activation layout (TB=128): act_u64[k*64 + j], j=0..63 packs rows (j, j+64).
// Warp reads lo = A[k*64+lane] (rows lane, lane+64) and
//            hi = A[k*64+32+lane] (rows lane+32, lane+96). Conflict-free.
// gemmP: NP output-PAIRS (transposed weights, ull = 2 adjacent outputs),
// accumulators: A0..A3 = rows lane / +32 / +64 / +96.
template <int NP, int KA, int KB, int ACT>
__device__ __forceinline__ void gemmP(
    const float* __restrict__ WTo, const float* __restrict__ bias, int o0,
    const float* __restrict__ actA, const float* __restrict__ actB,
    float* __restrict__ out, int lane)
{
    ull A0[NP], A1[NP], A2[NP], A3[NP];
#pragma unroll
    for (int p = 0; p < NP; p++) { A0[p] = A1[p] = A2[p] = A3[p] = 0ull; }
    {
        const ull* A = (const ull*)actA;
#pragma unroll 4
        for (int k = 0; k < KA; k++) {
            float2 lo = unpk(A[k * 64 + lane]);
            float2 hi = unpk(A[k * 64 + 32 + lane]);
            ull r0 = b2(lo.x), r1 = b2(hi.x), r2 = b2(lo.y), r3 = b2(hi.y);
#pragma unroll
            for (int p = 0; p < NP; p++) {
                ull w = *(const ull*)(WTo + (size_t)k * 100 + 2 * p);
                A0[p] = fma2(w, r0, A0[p]);
                A1[p] = fma2(w, r1, A1[p]);
                A2[p] = fma2(w, r2, A2[p]);
                A3[p] = fma2(w, r3, A3[p]);
            }
        }
    }
    if constexpr (KB > 0) {
        const ull* A = (const ull*)actB;
#pragma unroll 4
        for (int k = 0; k < KB; k++) {
            float2 lo = unpk(A[k * 64 + lane]);
            float2 hi = unpk(A[k * 64 + 32 + lane]);
            ull r0 = b2(lo.x), r1 = b2(hi.x), r2 = b2(lo.y), r3 = b2(hi.y);
#pragma unroll
            for (int p = 0; p < NP; p++) {
                ull w = *(const ull*)(WTo + (size_t)(KA + k) * 100 + 2 * p);
                A0[p] = fma2(w, r0, A0[p]);
                A1[p] = fma2(w, r1, A1[p]);
                A2[p] = fma2(w, r2, A2[p]);
                A3[p] = fma2(w, r3, A3[p]);
            }
        }
    }
    ull* o64 = (ull*)out;
#pragma unroll
    for (int p = 0; p < NP; p++) {
        const int o = o0 + 2 * p;
        const float bx = bias[o], by = bias[o + 1];
        float2 v0 = unpk(A0[p]), v1 = unpk(A1[p]);
        float2 v2 = unpk(A2[p]), v3 = unpk(A3[p]);
        o64[o * 64 + lane]            = pk(act_apply(v0.x + bx, ACT), act_apply(v2.x + bx, ACT));
        o64[o * 64 + 32 + lane]       = pk(act_apply(v1.x + bx, ACT), act_apply(v3.x + bx, ACT));
        o64[(o + 1) * 64 + lane]      = pk(act_apply(v0.y + by, ACT), act_apply(v2.y + by, ACT));
        o64[(o + 1) * 64 + 32 + lane] = pk(act_apply(v1.y + by, ACT), act_apply(v3.y + by, ACT));
    }
}

// Nout=100 = 50 pairs over 16 warps: warps 0-13 -> 3 pairs, 14/15 -> 4 pairs.
template <int KA, int KB, int ACT>
__device__ __forceinline__ void gemm100P(
    const float* __restrict__ WT, const float* __restrict__ bias,
    const float* aA, const float* aB, float* out, int warp, int lane)
{
    if (warp < 14)
        gemmP<3, KA, KB, ACT>(WT + 6 * warp, bias, 6 * warp, aA, aB, out, lane);
    else if (warp == 14)
        gemmP<4, KA, KB, ACT>(WT + 84, bias, 84, aA, aB, out, lane);
    else
        gemmP<4, KA, KB, ACT>(WT + 92, bias, 92, aA, aB, out, lane);
}

// ---------------------------------------------------------------------------
// Heads fused: warp w owns output o=w for all four heads; KL + z in registers.
// Row-pack accumulators (weights are scalars -> splat, acts stay packed).
__device__ __forceinline__ void heads_fused(
    const float* __restrict__ he, const float* __restrict__ hp,
    const float* __restrict__ bem, const float* __restrict__ bes,
    const float* __restrict__ bpm, const float* __restrict__ bps,
    const float* __restrict__ eps_t, float* __restrict__ zb,
    int warp, int lane, float& kl_acc)
{
    const int o = warp;                  // 16 warps == Z_DIM
    const float* WemT = g_WT + O_Wemu + o;
    const float* WesT = g_WT + O_Wesg + o;
    const float* WpmT = g_WT + O_Wpmu + o;
    const float* WpsT = g_WT + O_Wpsg + o;
    ull EM[2] = {0, 0}, ES[2] = {0, 0}, PM[2] = {0, 0}, PS[2] = {0, 0};
    const ull* He = (const ull*)he;
    const ull* Hp = (const ull*)hp;
#pragma unroll 4
    for (int k = 0; k < 100; k++) {
        ull eLo = He[k * 64 + lane];       // rows (lane, lane+64)
        ull eHi = He[k * 64 + 32 + lane];  // rows (lane+32, lane+96)
        ull qLo = Hp[k * 64 + lane];
        ull qHi = Hp[k * 64 + 32 + lane];
        ull wem = b2(WemT[k * 16]);
        ull wes = b2(WesT[k * 16]);
        ull wpm = b2(WpmT[k * 16]);
        ull wps = b2(WpsT[k * 16]);
        EM[0] = fma2(wem, eLo, EM[0]); EM[1] = fma2(wem, eHi, EM[1]);
        ES[0] = fma2(wes, eLo, ES[0]); ES[1] = fma2(wes, eHi, ES[1]);
        PM[0] = fma2(wpm, qLo, PM[0]); PM[1] = fma2(wpm, qHi, PM[1]);
        PS[0] = fma2(wps, qLo, PS[0]); PS[1] = fma2(wps, qHi, PS[1]);
    }
    const float bemv = bem[o], besv = bes[o], bpmv = bpm[o], bpsv = bps[o];
    float zv[4];                          // rows lane, +32, +64, +96
#pragma unroll
    for (int h = 0; h < 2; h++) {         // h=0: (lane, lane+64); h=1: (+32, +96)
        float2 em = unpk(EM[h]), es = unpk(ES[h]);
        float2 pm = unpk(PM[h]), ps = unpk(PS[h]);
#pragma unroll
        for (int e = 0; e < 2; e++) {     // e=0 -> .x (row), e=1 -> .y (row+64)
            float emu = (e ? em.y : em.x) + bemv;
            float esg = act_apply((e ? es.y : es.x) + besv, ACT_SP);
            float pmu = (e ? pm.y : pm.x) + bpmv;
            float psg = act_apply((e ? ps.y : ps.x) + bpsv, ACT_SP);
            float psx = psg + 1e-10f;
            float d   = emu - pmu;
            kl_acc += 0.5f * (2.f * logf(psx) - 2.f * logf(esg)
                              + (esg * esg + d * d) / (psx * psx) - 1.f);
            const int row = lane + 32 * h + 64 * e;
            zv[h + 2 * e] = emu + sqrtf(esg) * eps_t[(size_t)row * Z_DIM + o];
        }
    }
    ull* z64 = (ull*)zb;
    z64[o * 64 + lane]      = pk(zv[0], zv[2]);   // rows (lane, lane+64)
    z64[o * 64 + 32 + lane] = pk(zv[1], zv[3]);   // rows (lane+32, lane+96)
}

// ---------------------------------------------------------------------------
// GRU task = 4 adjacent j's (2 j-pairs). Gate columns: r +0, u +100, n +200.
__device__ __forceinline__ void gru_segT(
    ull (&R)[2][4], ull (&U)[2][4], ull (&NX)[2][4],
    const float* __restrict__ Wk, const float* __restrict__ act, int lane)
{
    const ull* A = (const ull*)act;
#pragma unroll 2
    for (int k = 0; k < 100; k++) {
        float2 lo = unpk(A[k * 64 + lane]);
        float2 hi = unpk(A[k * 64 + 32 + lane]);
        ull r0 = b2(lo.x), r1 = b2(hi.x), r2 = b2(lo.y), r3 = b2(hi.y);
        const float* w = Wk + (size_t)k * 300;
#pragma unroll
        for (int jp = 0; jp < 2; jp++) {
            ull wr = *(const ull*)(w + 2 * jp);
            ull wu = *(const ull*)(w + 100 + 2 * jp);
            ull wn = *(const ull*)(w + 200 + 2 * jp);
            R[jp][0]  = fma2(wr, r0, R[jp][0]);  R[jp][1]  = fma2(wr, r1, R[jp][1]);
            R[jp][2]  = fma2(wr, r2, R[jp][2]);  R[jp][3]  = fma2(wr, r3, R[jp][3]);
            U[jp][0]  = fma2(wu, r0, U[jp][0]);  U[jp][1]  = fma2(wu, r1, U[jp][1]);
            U[jp][2]  = fma2(wu, r2, U[jp][2]);  U[jp][3]  = fma2(wu, r3, U[jp][3]);
            NX[jp][0] = fma2(wn, r0, NX[jp][0]); NX[jp][1] = fma2(wn, r1, NX[jp][1]);
            NX[jp][2] = fma2(wn, r2, NX[jp][2]); NX[jp][3] = fma2(wn, r3, NX[jp][3]);
        }
    }
}

__device__ __forceinline__ void gru_task(
    int j0, const float* __restrict__ bih, const float* __restrict__ bhh,
    const float* __restrict__ pz, const float* __restrict__ px,
    const float* __restrict__ hc, float* __restrict__ hn, int lane)
{
    ull R[2][4], U[2][4], NI[2][4], NH[2][4];
#pragma unroll
    for (int p = 0; p < 2; p++)
#pragma unroll
        for (int r = 0; r < 4; r++) { R[p][r]=0; U[p][r]=0; NI[p][r]=0; NH[p][r]=0; }

    gru_segT(R, U, NI, g_WT + O_Wih + j0,             pz, lane);
    gru_segT(R, U, NI, g_WT + O_Wih + 100 * 300 + j0, px, lane);
    gru_segT(R, U, NH, g_WT + O_Whh + j0,             hc, lane);

    const ull* h64 = (const ull*)hc;
    ull* n64 = (ull*)hn;
#pragma unroll
    for (int jj = 0; jj < 4; jj++) {
        const int p = jj >> 1, e = jj & 1, j = j0 + jj;
        const float br = bih[j] + bhh[j];
        const float bu = bih[100 + j] + bhh[100 + j];
        const float bn = bih[200 + j];
        const float bm = bhh[200 + j];
        float2 Hlo = unpk(h64[j * 64 + lane]);       // rows lane, lane+64
        float2 Hhi = unpk(h64[j * 64 + 32 + lane]);  // rows lane+32, lane+96
        float hv[4] = { Hlo.x, Hhi.x, Hlo.y, Hhi.y };
        float ov[4];
#pragma unroll
        for (int r = 0; r < 4; r++) {
            float2 Rv = unpk(R[p][r]), Uv = unpk(U[p][r]);
            float2 Nv = unpk(NI[p][r]), Mv = unpk(NH[p][r]);
            float rv = e ? Rv.y : Rv.x;
            float uv = e ? Uv.y : Uv.x;
            float nv = e ? Nv.y : Nv.x;
            float mv = e ? Mv.y : Mv.x;
            float rr = sigf(rv + br);
            float uu = sigf(uv + bu);
            float nn = tanhf(nv + bn + rr * (mv + bm));
            ov[r] = (1.f - uu) * nn + uu * hv[r];
        }
        n64[j * 64 + lane]      = pk(ov[0], ov[2]);
        n64[j * 64 + 32 + lane] = pk(ov[1], ov[3]);
    }
}

// ---------------------------------------------------------------------------
// Wd3 (28 outputs = 14 pairs, warps 0-13) + fused Bernoulli NLL.
__device__ __forceinline__ void wd3_nll(
    const float* __restrict__ bd3, const float* __restrict__ hd2,
    const float* __restrict__ xs, int o0, int lane, float& nll)
{
    ull A0 = 0, A1 = 0, A2 = 0, A3 = 0;
    const ull* A = (const ull*)hd2;
    const float* WT3 = g_WT + O_Wd3 + o0;
#pragma unroll 4
    for (int k = 0; k < 100; k++) {
        float2 lo = unpk(A[k * 64 + lane]);
        float2 hi = unpk(A[k * 64 + 32 + lane]);
        ull w = *(const ull*)(WT3 + k * 28);
        A0 = fma2(w, b2(lo.x), A0);
        A1 = fma2(w, b2(hi.x), A1);
        A2 = fma2(w, b2(lo.y), A2);
        A3 = fma2(w, b2(hi.y), A3);
    }
    const ull* X = (const ull*)xs;
    float2 v[4] = { unpk(A0), unpk(A1), unpk(A2), unpk(A3) };
#pragma unroll
    for (int e = 0; e < 2; e++) {
        const int o = o0 + e;
        const float bv = bd3[o];
        float2 xlo = unpk(X[o * 64 + lane]);
        float2 xhi = unpk(X[o * 64 + 32 + lane]);
        float xv[4] = { xlo.x, xhi.x, xlo.y, xhi.y };
#pragma unroll
        for (int r = 0; r < 4; r++) {
            float pv = sigf((e ? v[r].y : v[r].x) + bv);
            nll -= xv[r] * logf(pv + 1e-10f)
                 + (1.f - xv[r]) * logf(1.f - pv + 1e-10f);
        }
    }
}

// ---------------------------------------------------------------------------
__global__ void __launch_bounds__(NTHR, 1) vrnn_main(
    const float* __restrict__ x,      const float* __restrict__ eps,
    const float* __restrict__ bpx,    const float* __restrict__ bpz,
    const float* __restrict__ bp1,    const float* __restrict__ bp_mu,
    const float* __restrict__ bp_sig, const float* __restrict__ be1,
    const float* __restrict__ be_mu,  const float* __restrict__ be_sig,
    const float* __restrict__ bd1,    const float* __restrict__ bd2,
    const float* __restrict__ bd3,    const float* __restrict__ bih,
    const float* __restrict__ bhh,    float* __restrict__ out)
{
    extern __shared__ float s[];
    float* xs = s;                        // 28*128
    float* zb = xs + X_DIM * TB;          // 16*128
    float* H0 = zb + Z_DIM * TB;          // 4 x 100*128
    float* H1 = H0 + H_DIM * TB;
    float* H2 = H1 + H_DIM * TB;
    float* H3 = H2 + H_DIM * TB;

    __shared__ int s_last;

    const int tid  = threadIdx.x;
    const int lane = tid & 31;
    const int warp = tid >> 5;
    const int b0   = blockIdx.x * TB;

    float* hc  = H0;   // current h
    float* pxb = H1;   // px / hd1
    float* s1  = H2;   // he / pz
    float* s2  = H3;   // hp / hn / hd2-free

    for (int i = tid; i < H_DIM * TB; i += NTHR) hc[i] = 0.f;

    float kl_acc = 0.f, nll_acc = 0.f;

    for (int t = 0; t < T_STEPS; t++) {
        const float* xg  = x   + ((size_t)t * B_TOT + b0) * X_DIM;
        const float* ept = eps + ((size_t)t * B_TOT + b0) * Z_DIM;
        for (int i = tid; i < X_DIM * TB; i += NTHR) {
            int r = i / X_DIM, k = i % X_DIM;
            xs[(k * 64 + (r & 63)) * 2 + (r >> 6)] = xg[i];
        }
        __syncthreads();

        // 1. px = relu(Wpx x + b) -> pxb
        gemm100P<28, 0, ACT_RELU>(g_WT + O_Wpx, bpx, xs, nullptr, pxb, warp, lane);
        __syncthreads();

        // 2+3. he = relu(We1 [px;h]) -> s1 ; hp = relu(Wp1 h) -> s2
        gemm100P<100, 100, ACT_RELU>(g_WT + O_We1, be1, pxb, hc, s1, warp, lane);
        gemm100P<100, 0,   ACT_RELU>(g_WT + O_Wp1, bp1, hc, nullptr, s2, warp, lane);
        __syncthreads();

        // 4. heads + KL + z -> zb (registers only otherwise)
        heads_fused(s1, s2, be_mu, be_sig, bp_mu, bp_sig, ept, zb,
                    warp, lane, kl_acc);
        __syncthreads();

        // 5. pz = relu(Wpz z + b) -> s1 (he dead)
        gemm100P<16, 0, ACT_RELU>(g_WT + O_Wpz, bpz, zb, nullptr, s1, warp, lane);
        __syncthreads();

        // 6. GRU(pz, px, h) -> hn into s2 (hp dead)
        for (int t4 = warp; t4 < 25; t4 += 16)
            gru_task(4 * t4, bih, bhh, s1, pxb, hc, s2, lane);
        __syncthreads();

        // 7. hd1 = relu(Wd1 [pz;h]) -> pxb (px dead after GRU)
        gemm100P<100, 100, ACT_RELU>(g_WT + O_Wd1, bd1, s1, hc, pxb, warp, lane);
        __syncthreads();

        // 8. hd2 = relu(Wd2 hd1) -> s1 (pz dead)
        gemm100P<100, 0, ACT_RELU>(g_WT + O_Wd2, bd2, pxb, nullptr, s1, warp, lane);
        __syncthreads();

        // 9. Wd3 + fused NLL (warps 0-13)
        if (warp < 14)
            wd3_nll(bd3, s1, xs, 2 * warp, lane, nll_acc);

        // rotate: new h = hn (s2); old hc becomes scratch
        { float* tmp = hc; hc = s2; s2 = tmp; }
        __syncthreads();
    }

    // ---- block partial reduction (16 warps)
#pragma unroll
    for (int off = 16; off > 0; off >>= 1) {
        kl_acc  += __shfl_down_sync(0xffffffffu, kl_acc,  off);
        nll_acc += __shfl_down_sync(0xffffffffu, nll_acc, off);
    }
    if (lane == 0) { s[warp] = kl_acc; s[16 + warp] = nll_acc; }
    __syncthreads();
    if (tid == 0) {
        float k = 0.f, n = 0.f;
        for (int w = 0; w < 16; w++) { k += s[w]; n += s[16 + w]; }
        g_part[2 * blockIdx.x + 0] = k;
        g_part[2 * blockIdx.x + 1] = n;
        __threadfence();
        unsigned v = atomicAdd(&g_done, 1u);
        s_last = (v == (unsigned)(gridDim.x - 1)) ? 1 : 0;
    }
    __syncthreads();

    // ---- deterministic final reduction in the last-arriving block
    if (s_last) {
        if (tid < NBLK) {
            s[tid]       = g_part[2 * tid + 0];
            s[NBLK + tid] = g_part[2 * tid + 1];
        }
        __syncthreads();
        for (int st = NBLK / 2; st > 0; st >>= 1) {
            if (tid < st) { s[tid] += s[tid + st]; s[NBLK + tid] += s[NBLK + tid + st]; }
            __syncthreads();
        }
        if (tid == 0) {
            const float invB = 1.f / (float)B_TOT;
            out[0] = s[0] * invB;
            out[1] = s[NBLK] * invB;
            g_done = 0;                  // reset for next graph replay
        }
    }
}

// ---------------------------------------------------------------------------
extern "C" void kernel_launch(void* const* d_in, const int* in_sizes, int n_in,
                              void* d_out, int out_size)
{
    (void)in_sizes; (void)n_in; (void)out_size;
    const float* x      = (const float*)d_in[0];
    const float* eps    = (const float*)d_in[1];
    const float* Wpx    = (const float*)d_in[2];
    const float* bpx    = (const float*)d_in[3];
    const float* Wpz    = (const float*)d_in[4];
    const float* bpz    = (const float*)d_in[5];
    const float* Wp1    = (const float*)d_in[6];
    const float* bp1    = (const float*)d_in[7];
    const float* Wp_mu  = (const float*)d_in[8];
    const float* bp_mu  = (const float*)d_in[9];
    const float* Wp_sig = (const float*)d_in[10];
    const float* bp_sig = (const float*)d_in[11];
    const float* We1    = (const float*)d_in[12];
    const float* be1    = (const float*)d_in[13];
    const float* We_mu  = (const float*)d_in[14];
    const float* be_mu  = (const float*)d_in[15];
    const float* We_sig = (const float*)d_in[16];
    const float* be_sig = (const float*)d_in[17];
    const float* Wd1    = (const float*)d_in[18];
    const float* bd1    = (const float*)d_in[19];
    const float* Wd2    = (const float*)d_in[20];
    const float* bd2    = (const float*)d_in[21];
    const float* Wd3    = (const float*)d_in[22];
    const float* bd3    = (const float*)d_in[23];
    const float* Wih    = (const float*)d_in[24];
    const float* Whh    = (const float*)d_in[25];
    const float* bih    = (const float*)d_in[26];
    const float* bhh    = (const float*)d_in[27];
    float* out = (float*)d_out;

    prep_transpose<<<160, 256>>>(Wpx, Wpz, Wp1, Wp_mu, Wp_sig, We_mu, We_sig,
                                 We1, Wd1, Wd2, Wd3, Wih, Whh);

    const int smem_floats = X_DIM * TB + Z_DIM * TB + 4 * H_DIM * TB;  // 56,832
    const int smem_bytes  = smem_floats * (int)sizeof(float);          // 227,328

    cudaFuncSetAttribute(vrnn_main,
                         cudaFuncAttributeMaxDynamicSharedMemorySize, smem_bytes);

    vrnn_main<<<NBLK, NTHR, smem_bytes>>>(
        x, eps, bpx, bpz, bp1, bp_mu, bp_sig, be1, be_mu, be_sig,
        bd1, bd2, bd3, bih, bhh, out);
}